// round 13
// baseline (speedup 1.0000x reference)
#include <cuda_runtime.h>
#include <cuda_bf16.h>
#include <math.h>
#include <stdint.h>

#define N_NODES 50000
#define N_EDGES 800000
#define HID     128
#define NHEAD   4
#define DH      32
#define OUTD    64

// ======================= scratch (device globals) ===========================
__device__ float g_q [N_NODES * HID];
__device__ float g_k [N_NODES * HID];
__device__ float g_v [N_NODES * HID];
__device__ float g_sk[N_NODES * HID];
__device__ float g_h [N_NODES * HID];
__device__ float g_t1[N_NODES * HID];
__device__ float g_t2[N_NODES * HID];
__device__ int   g_deg [N_NODES];
__device__ int   g_off [N_NODES + 1];
__device__ int   g_cur [N_NODES];
__device__ int   g_ssrc[N_EDGES];
__device__ float g_sattr[N_EDGES * 3];

#define SCAN_NBLK 49
__device__ int g_bsum[SCAN_NBLK];
__device__ int g_bpre[SCAN_NBLK];

__device__ __nv_bfloat16 g_xhi [N_NODES * HID];
__device__ __nv_bfloat16 g_xlo [N_NODES * HID];
__device__ __nv_bfloat16 g_hhi [N_NODES * HID];
__device__ __nv_bfloat16 g_hlo [N_NODES * HID];
__device__ __nv_bfloat16 g_t1hi[N_NODES * HID];
__device__ __nv_bfloat16 g_t1lo[N_NODES * HID];
__device__ __nv_bfloat16 g_t2hi[N_NODES * HID];
__device__ __nv_bfloat16 g_t2lo[N_NODES * HID];
__device__ __nv_bfloat16 g_whi[14 * 16384];
__device__ __nv_bfloat16 g_wlo[14 * 16384];

// ============ fused: weight split + x split (one launch) ====================
struct WPtrs { const float* p[14]; };

#define WSPLIT_BLOCKS 864
#define XSPLIT_BLOCKS 25000

__global__ void bigsplit_kernel(WPtrs wp, const float* __restrict__ x) {
    int b = blockIdx.x;
    if (b < WSPLIT_BLOCKS) {
        int mi, cb;
        if (b < 832) { mi = b >> 6; cb = b & 63; }
        else         { mi = 13;     cb = b - 832; }
        int i = cb * 256 + threadIdx.x;
        int n = (mi == 13) ? 8192 : 16384;
        if (i < n) {
            float v = wp.p[mi][i];
            __nv_bfloat16 h = __float2bfloat16(v);
            g_whi[mi * 16384 + i] = h;
            g_wlo[mi * 16384 + i] = __float2bfloat16(v - __bfloat162float(h));
        }
    } else {
        int i = (b - WSPLIT_BLOCKS) * 256 + threadIdx.x;
        float v = x[i];
        __nv_bfloat16 h = __float2bfloat16(v);
        g_xhi[i] = h;
        g_xlo[i] = __float2bfloat16(v - __bfloat162float(h));
    }
}

// ======================= edge sorting =======================================
__global__ void zero_deg_kernel() {
    int i = blockIdx.x * blockDim.x + threadIdx.x;
    if (i < N_NODES) g_deg[i] = 0;
}

__global__ void hist_kernel(const int* __restrict__ ei) {
    int e = blockIdx.x * blockDim.x + threadIdx.x;
    if (e < N_EDGES) atomicAdd(&g_deg[ei[N_EDGES + e]], 1);
}

__global__ __launch_bounds__(1024) void scan_s1() {
    __shared__ int wsum[32];
    int tid = threadIdx.x, lane = tid & 31, wid = tid >> 5;
    int i = blockIdx.x * 1024 + tid;
    int v = (i < N_NODES) ? g_deg[i] : 0;
    int x = v;
    #pragma unroll
    for (int d = 1; d < 32; d <<= 1) {
        int y = __shfl_up_sync(0xffffffffu, x, d);
        if (lane >= d) x += y;
    }
    if (lane == 31) wsum[wid] = x;
    __syncthreads();
    if (wid == 0) {
        int s = wsum[lane];
        #pragma unroll
        for (int d = 1; d < 32; d <<= 1) {
            int y = __shfl_up_sync(0xffffffffu, s, d);
            if (lane >= d) s += y;
        }
        wsum[lane] = s;
    }
    __syncthreads();
    int incl = x + (wid > 0 ? wsum[wid - 1] : 0);
    if (i < N_NODES) g_off[i] = incl - v;
    if (tid == 1023) g_bsum[blockIdx.x] = incl;
}

__global__ void scan_s2() {
    __shared__ int w0sum;
    int tid = threadIdx.x;
    int lane = tid & 31, wid = tid >> 5;
    int v = (tid < SCAN_NBLK) ? g_bsum[tid] : 0;
    int x = v;
    #pragma unroll
    for (int d = 1; d < 32; d <<= 1) {
        int y = __shfl_up_sync(0xffffffffu, x, d);
        if (lane >= d) x += y;
    }
    if (wid == 0 && lane == 31) w0sum = x;
    __syncthreads();
    int incl = x + (wid ? w0sum : 0);
    if (tid < SCAN_NBLK) g_bpre[tid] = incl - v;
    if (tid == SCAN_NBLK - 1) g_off[N_NODES] = incl;
}

__global__ void scan_s3() {
    int i = blockIdx.x * blockDim.x + threadIdx.x;
    if (i < N_NODES) {
        int o = g_off[i] + g_bpre[i >> 10];
        g_off[i] = o;
        g_cur[i] = o;
    }
}

__global__ void scatter_kernel(const int* __restrict__ ei, const float* __restrict__ attr) {
    int e = blockIdx.x * blockDim.x + threadIdx.x;
    if (e < N_EDGES) {
        int dst = ei[N_EDGES + e];
        int pos = atomicAdd(&g_cur[dst], 1);
        g_ssrc[pos] = ei[e];
        g_sattr[3 * pos + 0] = attr[3 * e + 0];
        g_sattr[3 * pos + 1] = attr[3 * e + 1];
        g_sattr[3 * pos + 2] = attr[3 * e + 2];
    }
}

// ======================= GELU ==============================================
__device__ __forceinline__ float gelu_f(float x) {
    float x3 = x * x * x;
    float u = 0.7978845608028654f * (x + 0.044715f * x3);
    return 0.5f * x * (1.0f + tanhf(u));
}

// ======================= HMMA GEMM common ===================================
#define SROW2 72

__device__ __forceinline__ void mma16816(float* c,
    uint32_t a0, uint32_t a1, uint32_t a2, uint32_t a3,
    uint32_t b0, uint32_t b1) {
    asm volatile(
        "mma.sync.aligned.m16n8k16.row.col.f32.bf16.bf16.f32 "
        "{%0,%1,%2,%3}, {%4,%5,%6,%7}, {%8,%9}, {%0,%1,%2,%3};"
        : "+f"(c[0]), "+f"(c[1]), "+f"(c[2]), "+f"(c[3])
        : "r"(a0), "r"(a1), "r"(a2), "r"(a3), "r"(b0), "r"(b1));
}

__device__ __forceinline__ void ldsm_x4(uint32_t& r0, uint32_t& r1,
                                        uint32_t& r2, uint32_t& r3, uint32_t addr) {
    asm volatile("ldmatrix.sync.aligned.m8n8.x4.shared.b16 {%0,%1,%2,%3}, [%4];"
                 : "=r"(r0), "=r"(r1), "=r"(r2), "=r"(r3) : "r"(addr));
}

__device__ __forceinline__ uint32_t smem_u32(const void* p) {
    return (uint32_t)__cvta_generic_to_shared(p);
}

__device__ __forceinline__ void stage_slab_A128(
    const __nv_bfloat16* Ahi, const __nv_bfloat16* Alo,
    __nv_bfloat16* sAh, __nv_bfloat16* sAl, int m0, int M, int slab, int tid)
{
    int row = tid >> 1;
    int u0  = (tid & 1) * 4;
    int gr  = m0 + row;
    bool ok = gr < M;
    const uint4* ah = (const uint4*)(Ahi + (size_t)gr * 128 + slab * 64);
    const uint4* al = (const uint4*)(Alo + (size_t)gr * 128 + slab * 64);
    uint4 z = make_uint4(0u, 0u, 0u, 0u);
    #pragma unroll
    for (int u = u0; u < u0 + 4; u++) {
        *(uint4*)(&sAh[row * SROW2 + u * 8]) = ok ? ah[u] : z;
        *(uint4*)(&sAl[row * SROW2 + u * 8]) = ok ? al[u] : z;
    }
}

__device__ __forceinline__ void stage_slab_A64(
    const __nv_bfloat16* Ahi, const __nv_bfloat16* Alo,
    __nv_bfloat16* sAh, __nv_bfloat16* sAl, int m0, int M, int slab, int tid)
{
    int row = tid >> 2;
    int u0  = (tid & 3) * 2;
    int gr  = m0 + row;
    bool ok = gr < M;
    const uint4* ah = (const uint4*)(Ahi + (size_t)gr * 128 + slab * 64);
    const uint4* al = (const uint4*)(Alo + (size_t)gr * 128 + slab * 64);
    uint4 z = make_uint4(0u, 0u, 0u, 0u);
    #pragma unroll
    for (int u = u0; u < u0 + 2; u++) {
        *(uint4*)(&sAh[row * SROW2 + u * 8]) = ok ? ah[u] : z;
        *(uint4*)(&sAl[row * SROW2 + u * 8]) = ok ? al[u] : z;
    }
}

__device__ __forceinline__ void stage_slab_B(
    const __nv_bfloat16* Bhi, const __nv_bfloat16* Blo,
    __nv_bfloat16* sBh, __nv_bfloat16* sBl, int Nout, int slab, int tid)
{
    int row = tid >> 1;
    if (row < Nout) {
        int u0 = (tid & 1) * 4;
        const uint4* bh = (const uint4*)(Bhi + (size_t)row * 128 + slab * 64);
        const uint4* bl = (const uint4*)(Blo + (size_t)row * 128 + slab * 64);
        #pragma unroll
        for (int u = u0; u < u0 + 4; u++) {
            *(uint4*)(&sBh[row * SROW2 + u * 8]) = bh[u];
            *(uint4*)(&sBl[row * SROW2 + u * 8]) = bl[u];
        }
    }
}

__device__ __forceinline__ void mainloop_slab(
    const __nv_bfloat16* sAh, const __nv_bfloat16* sAl,
    const __nv_bfloat16* sBh, const __nv_bfloat16* sBl,
    float acc[2][8][4], int mt, int lane, int ntBeg, int ntN)
{
    uint32_t aAh = smem_u32(sAh), aAl = smem_u32(sAl);
    uint32_t aBh = smem_u32(sBh), aBl = smem_u32(sBl);
    int arow = lane & 15, akh = 8 * (lane >> 4);
    int brow = lane & 7;
    int bsel = lane >> 4;
    int bk   = 8 * ((lane >> 3) & 1);

    for (int kt = 0; kt < 64; kt += 16) {
        uint32_t ah[2][4], al[2][4];
        #pragma unroll
        for (int mi = 0; mi < 2; mi++) {
            int aoff = (mt + mi * 16 + arow) * SROW2 + akh + kt;
            ldsm_x4(ah[mi][0], ah[mi][1], ah[mi][2], ah[mi][3], aAh + (uint32_t)aoff * 2);
            ldsm_x4(al[mi][0], al[mi][1], al[mi][2], al[mi][3], aAl + (uint32_t)aoff * 2);
        }
        #pragma unroll
        for (int p = 0; p < 4; p++) {
            if (2 * p >= ntN) break;
            int nt = ntBeg + 2 * p + bsel;
            int boff = (nt * 8 + brow) * SROW2 + bk + kt;
            uint32_t bh0, bh1, bh2, bh3, bl0, bl1, bl2, bl3;
            ldsm_x4(bh0, bh1, bh2, bh3, aBh + (uint32_t)boff * 2);
            ldsm_x4(bl0, bl1, bl2, bl3, aBl + (uint32_t)boff * 2);
            #pragma unroll
            for (int mi = 0; mi < 2; mi++) {
                mma16816(acc[mi][2 * p + 0], ah[mi][0], ah[mi][1], ah[mi][2], ah[mi][3], bh0, bh1);
                mma16816(acc[mi][2 * p + 0], ah[mi][0], ah[mi][1], ah[mi][2], ah[mi][3], bl0, bl1);
                mma16816(acc[mi][2 * p + 0], al[mi][0], al[mi][1], al[mi][2], al[mi][3], bh0, bh1);
                mma16816(acc[mi][2 * p + 1], ah[mi][0], ah[mi][1], ah[mi][2], ah[mi][3], bh2, bh3);
                mma16816(acc[mi][2 * p + 1], ah[mi][0], ah[mi][1], ah[mi][2], ah[mi][3], bl2, bl3);
                mma16816(acc[mi][2 * p + 1], al[mi][0], al[mi][1], al[mi][2], al[mi][3], bh2, bh3);
            }
        }
    }
}

// ======================= mma_gemm: 64-row CTAs ==============================
#define OFF3_AH 0
#define OFF3_AL 9216
#define OFF3_BH 18432
#define OFF3_BL 36864
#define MMA_SMEM3 55296

__global__ __launch_bounds__(256, 2) void mma_gemm(
    const __nv_bfloat16* __restrict__ Ahi, const __nv_bfloat16* __restrict__ Alo,
    const __nv_bfloat16* __restrict__ Bhi, const __nv_bfloat16* __restrict__ Blo,
    const float* __restrict__ bias, const float* __restrict__ res,
    float* __restrict__ C, __nv_bfloat16* __restrict__ Chi, __nv_bfloat16* __restrict__ Clo,
    int M, int Nout, int act)
{
    extern __shared__ char smem[];
    __nv_bfloat16* sAh = (__nv_bfloat16*)(smem + OFF3_AH);
    __nv_bfloat16* sAl = (__nv_bfloat16*)(smem + OFF3_AL);
    __nv_bfloat16* sBh = (__nv_bfloat16*)(smem + OFF3_BH);
    __nv_bfloat16* sBl = (__nv_bfloat16*)(smem + OFF3_BL);
    int tid = threadIdx.x;
    int m0 = blockIdx.x * 64;

    int lane = tid & 31, wid = tid >> 5;
    int grp = lane >> 2, qd = lane & 3;
    int mt = (wid >> 2) * 32;
    int NT = Nout >> 3;
    int ntBeg = (wid & 3) * (NT >> 2);
    int ntN   = NT >> 2;

    float acc[2][8][4];
    #pragma unroll
    for (int mi = 0; mi < 2; mi++)
        #pragma unroll
        for (int i = 0; i < 8; i++)
            #pragma unroll
            for (int j = 0; j < 4; j++) acc[mi][i][j] = 0.f;

    #pragma unroll
    for (int s = 0; s < 2; s++) {
        if (s) __syncthreads();
        stage_slab_A64(Ahi, Alo, sAh, sAl, m0, M, s, tid);
        stage_slab_B(Bhi, Blo, sBh, sBl, Nout, s, tid);
        __syncthreads();
        mainloop_slab(sAh, sAl, sBh, sBl, acc, mt, lane, ntBeg, ntN);
    }

    #pragma unroll
    for (int mi = 0; mi < 2; mi++) {
        #pragma unroll
        for (int t = 0; t < 8; t++) {
            if (t >= ntN) break;
            int col = (ntBeg + t) * 8 + 2 * qd;
            float bsum0 = bias ? bias[col]     : 0.f;
            float bsum1 = bias ? bias[col + 1] : 0.f;
            #pragma unroll
            for (int half = 0; half < 2; half++) {
                int row = m0 + mt + mi * 16 + grp + half * 8;
                if (row >= M) continue;
                float v0 = acc[mi][t][half * 2 + 0] + bsum0;
                float v1 = acc[mi][t][half * 2 + 1] + bsum1;
                if (act) { v0 = gelu_f(v0); v1 = gelu_f(v1); }
                size_t base = (size_t)row * Nout + col;
                if (res) { v0 += res[base]; v1 += res[base + 1]; }
                *(float2*)(C + base) = make_float2(v0, v1);
                if (Chi) {
                    __nv_bfloat16 h0 = __float2bfloat16(v0);
                    __nv_bfloat16 h1 = __float2bfloat16(v1);
                    __nv_bfloat162 hh; hh.x = h0; hh.y = h1;
                    __nv_bfloat162 ll;
                    ll.x = __float2bfloat16(v0 - __bfloat162float(h0));
                    ll.y = __float2bfloat16(v1 - __bfloat162float(h1));
                    *(__nv_bfloat162*)(Chi + base) = hh;
                    *(__nv_bfloat162*)(Clo + base) = ll;
                }
            }
        }
    }
}

// ======================= qkvs_gemm: 128-row CTAs, 2 CTAs/SM =================
#define OFF2_AH 0
#define OFF2_AL 18432
#define OFF2_BH 36864
#define OFF2_BL 55296
#define MMA_SMEM2 73728

struct QkvsPtrs {
    const __nv_bfloat16 *bh[4], *bl[4];
    float* c[4];
};

__global__ __launch_bounds__(256, 2) void qkvs_gemm(
    const __nv_bfloat16* __restrict__ Ahi, const __nv_bfloat16* __restrict__ Alo,
    QkvsPtrs pp, int M)
{
    extern __shared__ char smem[];
    __nv_bfloat16* sAh = (__nv_bfloat16*)(smem + OFF2_AH);
    __nv_bfloat16* sAl = (__nv_bfloat16*)(smem + OFF2_AL);
    __nv_bfloat16* sBh = (__nv_bfloat16*)(smem + OFF2_BH);
    __nv_bfloat16* sBl = (__nv_bfloat16*)(smem + OFF2_BL);
    int tid = threadIdx.x;
    int m0 = blockIdx.x * 128;
    int sel = blockIdx.y;

    int lane = tid & 31, wid = tid >> 5;
    int grp = lane >> 2, qd = lane & 3;
    int mt = (wid >> 1) * 32;
    int ntBeg = (wid & 1) * 8;

    float acc[2][8][4];
    #pragma unroll
    for (int mi = 0; mi < 2; mi++)
        #pragma unroll
        for (int i = 0; i < 8; i++)
            #pragma unroll
            for (int j = 0; j < 4; j++) acc[mi][i][j] = 0.f;

    #pragma unroll
    for (int s = 0; s < 2; s++) {
        if (s) __syncthreads();
        stage_slab_A128(Ahi, Alo, sAh, sAl, m0, M, s, tid);
        stage_slab_B(pp.bh[sel], pp.bl[sel], sBh, sBl, HID, s, tid);
        __syncthreads();
        mainloop_slab(sAh, sAl, sBh, sBl, acc, mt, lane, ntBeg, 8);
    }

    float* C = pp.c[sel];
    #pragma unroll
    for (int mi = 0; mi < 2; mi++) {
        #pragma unroll
        for (int t = 0; t < 8; t++) {
            int col = (ntBeg + t) * 8 + 2 * qd;
            #pragma unroll
            for (int half = 0; half < 2; half++) {
                int row = m0 + mt + mi * 16 + grp + half * 8;
                if (row >= M) continue;
                size_t base = (size_t)row * HID + col;
                *(float2*)(C + base) = make_float2(acc[mi][t][half * 2], acc[mi][t][half * 2 + 1]);
            }
        }
    }
}

// ======= edge attention: FOUR independent online-softmax accumulators =======
__global__ __launch_bounds__(128) void attn_kernel(
    const float* __restrict__ q, const float* __restrict__ k,
    const float* __restrict__ v, const float* __restrict__ skip,
    const float* __restrict__ We, float* __restrict__ out,
    __nv_bfloat16* __restrict__ outhi, __nv_bfloat16* __restrict__ outlo)
{
    __shared__ float we_s[HID * 3];
    int tid = threadIdx.x;
    for (int i = tid; i < HID * 3; i += blockDim.x) we_s[i] = We[i];
    __syncthreads();

    int warp = blockIdx.x * (blockDim.x >> 5) + (tid >> 5);
    if (warp >= N_NODES) return;
    int lane = tid & 31;
    int col  = (lane >> 3) * DH + (lane & 7) * 4;

    float wr[12];
    #pragma unroll
    for (int i = 0; i < 4; i++)
        #pragma unroll
        for (int c = 0; c < 3; c++)
            wr[i * 3 + c] = we_s[3 * (col + i) + c];

    float4 qv = *(const float4*)(q + (size_t)warp * HID + col);

    // four independent accumulators
    float m_[4], s_[4], ox_[4], oy_[4], oz_[4], ow_[4];
    #pragma unroll
    for (int j = 0; j < 4; j++) {
        m_[j] = -INFINITY; s_[j] = 0.f;
        ox_[j] = 0.f; oy_[j] = 0.f; oz_[j] = 0.f; ow_[j] = 0.f;
    }

    int e0 = g_off[warp], e1 = g_off[warp + 1];
    int e = e0;
    for (; e + 4 <= e1; e += 4) {
        int srcs[4];
        float at[4][3];
        float4 kvs[4], vvs[4];
        #pragma unroll
        for (int j = 0; j < 4; j++) srcs[j] = g_ssrc[e + j];
        #pragma unroll
        for (int j = 0; j < 4; j++) {
            at[j][0] = g_sattr[3 * (e + j) + 0];
            at[j][1] = g_sattr[3 * (e + j) + 1];
            at[j][2] = g_sattr[3 * (e + j) + 2];
        }
        #pragma unroll
        for (int j = 0; j < 4; j++) {
            kvs[j] = *(const float4*)(k + (size_t)srcs[j] * HID + col);
            vvs[j] = *(const float4*)(v + (size_t)srcs[j] * HID + col);
        }

        float ec[4][4], d[4];
        #pragma unroll
        for (int j = 0; j < 4; j++) {
            ec[j][0] = fmaf(at[j][0], wr[0], fmaf(at[j][1], wr[1],  at[j][2] * wr[2]));
            ec[j][1] = fmaf(at[j][0], wr[3], fmaf(at[j][1], wr[4],  at[j][2] * wr[5]));
            ec[j][2] = fmaf(at[j][0], wr[6], fmaf(at[j][1], wr[7],  at[j][2] * wr[8]));
            ec[j][3] = fmaf(at[j][0], wr[9], fmaf(at[j][1], wr[10], at[j][2] * wr[11]));
            d[j] = qv.x * (kvs[j].x + ec[j][0]) + qv.y * (kvs[j].y + ec[j][1])
                 + qv.z * (kvs[j].z + ec[j][2]) + qv.w * (kvs[j].w + ec[j][3]);
        }
        // interleaved butterflies: 4 independent chains
        #pragma unroll
        for (int st = 1; st <= 4; st <<= 1) {
            #pragma unroll
            for (int j = 0; j < 4; j++)
                d[j] += __shfl_xor_sync(0xffffffffu, d[j], st);
        }
        // per-accumulator online softmax update (independent chains)
        #pragma unroll
        for (int j = 0; j < 4; j++) {
            float alpha = d[j] * 0.17677669529663687f;
            float nm = fmaxf(m_[j], alpha);
            float sc = __expf(m_[j] - nm);
            float p  = __expf(alpha - nm);
            s_[j] = s_[j] * sc + p;
            ox_[j] = ox_[j] * sc + p * (vvs[j].x + ec[j][0]);
            oy_[j] = oy_[j] * sc + p * (vvs[j].y + ec[j][1]);
            oz_[j] = oz_[j] * sc + p * (vvs[j].z + ec[j][2]);
            ow_[j] = ow_[j] * sc + p * (vvs[j].w + ec[j][3]);
            m_[j] = nm;
        }
    }
    // remainder -> accumulator 0
    for (; e < e1; e++) {
        int src = g_ssrc[e];
        float a0 = g_sattr[3 * e + 0];
        float a1 = g_sattr[3 * e + 1];
        float a2 = g_sattr[3 * e + 2];
        float4 kv = *(const float4*)(k + (size_t)src * HID + col);
        float4 vv = *(const float4*)(v + (size_t)src * HID + col);
        float ec0 = fmaf(a0, wr[0], fmaf(a1, wr[1],  a2 * wr[2]));
        float ec1 = fmaf(a0, wr[3], fmaf(a1, wr[4],  a2 * wr[5]));
        float ec2 = fmaf(a0, wr[6], fmaf(a1, wr[7],  a2 * wr[8]));
        float ec3 = fmaf(a0, wr[9], fmaf(a1, wr[10], a2 * wr[11]));
        float dot = qv.x * (kv.x + ec0) + qv.y * (kv.y + ec1)
                  + qv.z * (kv.z + ec2) + qv.w * (kv.w + ec3);
        dot += __shfl_xor_sync(0xffffffffu, dot, 1);
        dot += __shfl_xor_sync(0xffffffffu, dot, 2);
        dot += __shfl_xor_sync(0xffffffffu, dot, 4);
        float alpha = dot * 0.17677669529663687f;
        float nm = fmaxf(m_[0], alpha);
        float sc = __expf(m_[0] - nm);
        float p  = __expf(alpha - nm);
        s_[0] = s_[0] * sc + p;
        ox_[0] = ox_[0] * sc + p * (vv.x + ec0);
        oy_[0] = oy_[0] * sc + p * (vv.y + ec1);
        oz_[0] = oz_[0] * sc + p * (vv.z + ec2);
        ow_[0] = ow_[0] * sc + p * (vv.w + ec3);
        m_[0] = nm;
    }

    // pairwise exact merges: (0<-1), (2<-3), (0<-2)
    #pragma unroll
    for (int step = 0; step < 3; step++) {
        int a = (step == 0) ? 0 : (step == 1) ? 2 : 0;
        int b = (step == 0) ? 1 : (step == 1) ? 3 : 2;
        float nm = fmaxf(m_[a], m_[b]);
        float wa = (m_[a] == -INFINITY) ? 0.f : __expf(m_[a] - nm);
        float wb = (m_[b] == -INFINITY) ? 0.f : __expf(m_[b] - nm);
        s_[a] = s_[a] * wa + s_[b] * wb;
        ox_[a] = ox_[a] * wa + ox_[b] * wb;
        oy_[a] = oy_[a] * wa + oy_[b] * wb;
        oz_[a] = oz_[a] * wa + oz_[b] * wb;
        ow_[a] = ow_[a] * wa + ow_[b] * wb;
        m_[a] = nm;
    }

    float inv = 1.0f / fmaxf(s_[0], 1e-16f);
    float4 sk = *(const float4*)(skip + (size_t)warp * HID + col);
    float o0 = ox_[0] * inv + sk.x, o1 = oy_[0] * inv + sk.y;
    float o2 = oz_[0] * inv + sk.z, o3 = ow_[0] * inv + sk.w;
    size_t base = (size_t)warp * HID + col;
    *(float4*)(out + base) = make_float4(o0, o1, o2, o3);

    float vs[4] = {o0, o1, o2, o3};
    #pragma unroll
    for (int pr = 0; pr < 2; pr++) {
        float v0 = vs[pr * 2], v1 = vs[pr * 2 + 1];
        __nv_bfloat16 h0 = __float2bfloat16(v0);
        __nv_bfloat16 h1 = __float2bfloat16(v1);
        __nv_bfloat162 hh; hh.x = h0; hh.y = h1;
        __nv_bfloat162 ll;
        ll.x = __float2bfloat16(v0 - __bfloat162float(h0));
        ll.y = __float2bfloat16(v1 - __bfloat162float(h1));
        *(__nv_bfloat162*)(outhi + base + pr * 2) = hh;
        *(__nv_bfloat162*)(outlo + base + pr * 2) = ll;
    }
}

// ======================= launch =============================================
static inline void run_mm(cudaStream_t s,
                          const __nv_bfloat16* Ahi, const __nv_bfloat16* Alo,
                          const __nv_bfloat16* Bhi, const __nv_bfloat16* Blo,
                          const float* bias, const float* res,
                          float* C, __nv_bfloat16* Chi, __nv_bfloat16* Clo,
                          int M, int Nout, int act) {
    int grid = (M + 63) / 64;
    mma_gemm<<<grid, 256, MMA_SMEM3, s>>>(Ahi, Alo, Bhi, Blo, bias, res, C, Chi, Clo, M, Nout, act);
}

extern "C" void kernel_launch(void* const* d_in, const int* in_sizes, int n_in,
                              void* d_out, int out_size) {
    const float* x    = (const float*)d_in[0];
    const int*   ei   = (const int*)  d_in[1];
    const float* attr = (const float*)d_in[2];
    const float* Wq1 = (const float*)d_in[3],  *Wk1 = (const float*)d_in[4];
    const float* Wv1 = (const float*)d_in[5],  *We1 = (const float*)d_in[6];
    const float* Ws1 = (const float*)d_in[7];
    const float* M1a = (const float*)d_in[8],  *b1a = (const float*)d_in[9];
    const float* M1b = (const float*)d_in[10], *b1b = (const float*)d_in[11];
    const float* Wq2 = (const float*)d_in[12], *Wk2 = (const float*)d_in[13];
    const float* Wv2 = (const float*)d_in[14], *We2 = (const float*)d_in[15];
    const float* Ws2 = (const float*)d_in[16];
    const float* M2a = (const float*)d_in[17], *b2a = (const float*)d_in[18];
    const float* M2b = (const float*)d_in[19], *b2b = (const float*)d_in[20];
    const float* Wf1 = (const float*)d_in[21], *bf1 = (const float*)d_in[22];
    const float* Wf2 = (const float*)d_in[23], *bf2 = (const float*)d_in[24];
    float* out = (float*)d_out;

    float *q, *k, *v, *sk, *h, *t1, *t2;
    cudaGetSymbolAddress((void**)&q,  g_q);
    cudaGetSymbolAddress((void**)&k,  g_k);
    cudaGetSymbolAddress((void**)&v,  g_v);
    cudaGetSymbolAddress((void**)&sk, g_sk);
    cudaGetSymbolAddress((void**)&h,  g_h);
    cudaGetSymbolAddress((void**)&t1, g_t1);
    cudaGetSymbolAddress((void**)&t2, g_t2);

    __nv_bfloat16 *xhi, *xlo, *hhi, *hlo, *t1hi, *t1lo, *t2hi, *t2lo, *whi, *wlo;
    cudaGetSymbolAddress((void**)&xhi,  g_xhi);
    cudaGetSymbolAddress((void**)&xlo,  g_xlo);
    cudaGetSymbolAddress((void**)&hhi,  g_hhi);
    cudaGetSymbolAddress((void**)&hlo,  g_hlo);
    cudaGetSymbolAddress((void**)&t1hi, g_t1hi);
    cudaGetSymbolAddress((void**)&t1lo, g_t1lo);
    cudaGetSymbolAddress((void**)&t2hi, g_t2hi);
    cudaGetSymbolAddress((void**)&t2lo, g_t2lo);
    cudaGetSymbolAddress((void**)&whi,  g_whi);
    cudaGetSymbolAddress((void**)&wlo,  g_wlo);

    cudaFuncSetAttribute(mma_gemm,  cudaFuncAttributeMaxDynamicSharedMemorySize, MMA_SMEM3);
    cudaFuncSetAttribute(qkvs_gemm, cudaFuncAttributeMaxDynamicSharedMemorySize, MMA_SMEM2);

    static cudaStream_t s_side = nullptr;
    static cudaEvent_t ev_fork = nullptr, ev_join = nullptr;
    if (!s_side) {
        cudaStreamCreateWithFlags(&s_side, cudaStreamNonBlocking);
        cudaEventCreateWithFlags(&ev_fork, cudaEventDisableTiming);
        cudaEventCreateWithFlags(&ev_join, cudaEventDisableTiming);
    }

    cudaStream_t s = 0;
    #define WHI(i) (whi + (i) * 16384)
    #define WLO(i) (wlo + (i) * 16384)

    int gblocks = (N_NODES + 127) / 128;
    int ablocks = (N_NODES * 32 + 127) / 128;

    // ---- fork: side stream runs the edge-sort chain concurrently ----
    cudaEventRecord(ev_fork, s);
    cudaStreamWaitEvent(s_side, ev_fork, 0);

    zero_deg_kernel<<<(N_NODES + 255) / 256, 256, 0, s_side>>>();
    hist_kernel<<<(N_EDGES + 255) / 256, 256, 0, s_side>>>(ei);

    WPtrs wp;
    const float* wsrc[14] = {Wq1, Wk1, Wv1, Ws1, M1a, M1b, Wq2, Wk2, Wv2, Ws2, M2a, M2b, Wf1, Wf2};
    for (int i = 0; i < 14; i++) wp.p[i] = wsrc[i];
    bigsplit_kernel<<<WSPLIT_BLOCKS + XSPLIT_BLOCKS, 256, 0, s>>>(wp, x);

    QkvsPtrs p1;
    for (int i = 0; i < 4; i++) { p1.bh[i] = WHI(i); p1.bl[i] = WLO(i); }
    p1.c[0] = q; p1.c[1] = k; p1.c[2] = v; p1.c[3] = sk;
    qkvs_gemm<<<dim3(gblocks, 4), 256, MMA_SMEM2, s>>>(xhi, xlo, p1, N_NODES);

    scan_s1<<<SCAN_NBLK, 1024, 0, s_side>>>();
    scan_s2<<<1, 64, 0, s_side>>>();
    scan_s3<<<(N_NODES + 255) / 256, 256, 0, s_side>>>();
    scatter_kernel<<<(N_EDGES + 255) / 256, 256, 0, s_side>>>(ei, attr);

    cudaEventRecord(ev_join, s_side);
    cudaStreamWaitEvent(s, ev_join, 0);

    // layer 1
    attn_kernel<<<ablocks, 128, 0, s>>>(q, k, v, sk, We1, h, hhi, hlo);
    run_mm(s, hhi,  hlo,  WHI(4), WLO(4), b1a, nullptr, t1, t1hi, t1lo, N_NODES, HID, 1);
    run_mm(s, t1hi, t1lo, WHI(5), WLO(5), b1b, h,       t2, t2hi, t2lo, N_NODES, HID, 1);

    // layer 2
    QkvsPtrs p2;
    for (int i = 0; i < 4; i++) { p2.bh[i] = WHI(6 + i); p2.bl[i] = WLO(6 + i); }
    p2.c[0] = q; p2.c[1] = k; p2.c[2] = v; p2.c[3] = sk;
    qkvs_gemm<<<dim3(gblocks, 4), 256, MMA_SMEM2, s>>>(t2hi, t2lo, p2, N_NODES);
    attn_kernel<<<ablocks, 128, 0, s>>>(q, k, v, sk, We2, h, hhi, hlo);
    run_mm(s, hhi,  hlo,  WHI(10), WLO(10), b2a, nullptr, t1, t1hi, t1lo, N_NODES, HID, 1);
    run_mm(s, t1hi, t1lo, WHI(11), WLO(11), b2b, h,       t2, t2hi, t2lo, N_NODES, HID, 1);

    // final MLP
    run_mm(s, t2hi, t2lo, WHI(12), WLO(12), bf1, nullptr, t1, t1hi, t1lo, N_NODES, HID, 1);
    run_mm(s, t1hi, t1lo, WHI(13), WLO(13), bf2, nullptr, out, nullptr, nullptr, N_NODES, OUTD, 1);
}

// round 14
// speedup vs baseline: 1.0253x; 1.0253x over previous
#include <cuda_runtime.h>
#include <cuda_bf16.h>
#include <math.h>
#include <stdint.h>

#define N_NODES 50000
#define N_EDGES 800000
#define HID     128
#define NHEAD   4
#define DH      32
#define OUTD    64

// ======================= scratch (device globals) ===========================
__device__ float g_q [N_NODES * HID];
__device__ float g_k [N_NODES * HID];
__device__ float g_v [N_NODES * HID];
__device__ float g_sk[N_NODES * HID];
__device__ float g_h [N_NODES * HID];
__device__ float g_t1[N_NODES * HID];
__device__ float g_t2[N_NODES * HID];
__device__ int   g_deg [N_NODES];
__device__ int   g_off [N_NODES + 1];
__device__ int   g_cur [N_NODES];
__device__ int   g_ssrc[N_EDGES];
__device__ float g_sattr[N_EDGES * 3];

#define SCAN_NBLK 49
__device__ int g_bsum[SCAN_NBLK];
__device__ int g_bpre[SCAN_NBLK];

__device__ __nv_bfloat16 g_xhi [N_NODES * HID];
__device__ __nv_bfloat16 g_xlo [N_NODES * HID];
__device__ __nv_bfloat16 g_hhi [N_NODES * HID];
__device__ __nv_bfloat16 g_hlo [N_NODES * HID];
__device__ __nv_bfloat16 g_t1hi[N_NODES * HID];
__device__ __nv_bfloat16 g_t1lo[N_NODES * HID];
__device__ __nv_bfloat16 g_t2hi[N_NODES * HID];
__device__ __nv_bfloat16 g_t2lo[N_NODES * HID];
__device__ __nv_bfloat16 g_whi[14 * 16384];
__device__ __nv_bfloat16 g_wlo[14 * 16384];

// ============ fused: weight split + x split (one launch) ====================
struct WPtrs { const float* p[14]; };

#define WSPLIT_BLOCKS 864
#define XSPLIT_BLOCKS 25000

__global__ void bigsplit_kernel(WPtrs wp, const float* __restrict__ x) {
    int b = blockIdx.x;
    if (b < WSPLIT_BLOCKS) {
        int mi, cb;
        if (b < 832) { mi = b >> 6; cb = b & 63; }
        else         { mi = 13;     cb = b - 832; }
        int i = cb * 256 + threadIdx.x;
        int n = (mi == 13) ? 8192 : 16384;
        if (i < n) {
            float v = wp.p[mi][i];
            __nv_bfloat16 h = __float2bfloat16(v);
            g_whi[mi * 16384 + i] = h;
            g_wlo[mi * 16384 + i] = __float2bfloat16(v - __bfloat162float(h));
        }
    } else {
        int i = (b - WSPLIT_BLOCKS) * 256 + threadIdx.x;
        float v = x[i];
        __nv_bfloat16 h = __float2bfloat16(v);
        g_xhi[i] = h;
        g_xlo[i] = __float2bfloat16(v - __bfloat162float(h));
    }
}

// ======================= edge sorting =======================================
__global__ void zero_deg_kernel() {
    int i = blockIdx.x * blockDim.x + threadIdx.x;
    if (i < N_NODES) g_deg[i] = 0;
}

__global__ void hist_kernel(const int* __restrict__ ei) {
    int e = blockIdx.x * blockDim.x + threadIdx.x;
    if (e < N_EDGES) atomicAdd(&g_deg[ei[N_EDGES + e]], 1);
}

__global__ __launch_bounds__(1024) void scan_s1() {
    __shared__ int wsum[32];
    int tid = threadIdx.x, lane = tid & 31, wid = tid >> 5;
    int i = blockIdx.x * 1024 + tid;
    int v = (i < N_NODES) ? g_deg[i] : 0;
    int x = v;
    #pragma unroll
    for (int d = 1; d < 32; d <<= 1) {
        int y = __shfl_up_sync(0xffffffffu, x, d);
        if (lane >= d) x += y;
    }
    if (lane == 31) wsum[wid] = x;
    __syncthreads();
    if (wid == 0) {
        int s = wsum[lane];
        #pragma unroll
        for (int d = 1; d < 32; d <<= 1) {
            int y = __shfl_up_sync(0xffffffffu, s, d);
            if (lane >= d) s += y;
        }
        wsum[lane] = s;
    }
    __syncthreads();
    int incl = x + (wid > 0 ? wsum[wid - 1] : 0);
    if (i < N_NODES) g_off[i] = incl - v;
    if (tid == 1023) g_bsum[blockIdx.x] = incl;
}

__global__ void scan_s2() {
    __shared__ int w0sum;
    int tid = threadIdx.x;
    int lane = tid & 31, wid = tid >> 5;
    int v = (tid < SCAN_NBLK) ? g_bsum[tid] : 0;
    int x = v;
    #pragma unroll
    for (int d = 1; d < 32; d <<= 1) {
        int y = __shfl_up_sync(0xffffffffu, x, d);
        if (lane >= d) x += y;
    }
    if (wid == 0 && lane == 31) w0sum = x;
    __syncthreads();
    int incl = x + (wid ? w0sum : 0);
    if (tid < SCAN_NBLK) g_bpre[tid] = incl - v;
    if (tid == SCAN_NBLK - 1) g_off[N_NODES] = incl;
}

__global__ void scan_s3() {
    int i = blockIdx.x * blockDim.x + threadIdx.x;
    if (i < N_NODES) {
        int o = g_off[i] + g_bpre[i >> 10];
        g_off[i] = o;
        g_cur[i] = o;
    }
}

__global__ void scatter_kernel(const int* __restrict__ ei, const float* __restrict__ attr) {
    int e = blockIdx.x * blockDim.x + threadIdx.x;
    if (e < N_EDGES) {
        int dst = ei[N_EDGES + e];
        int pos = atomicAdd(&g_cur[dst], 1);
        g_ssrc[pos] = ei[e];
        g_sattr[3 * pos + 0] = attr[3 * e + 0];
        g_sattr[3 * pos + 1] = attr[3 * e + 1];
        g_sattr[3 * pos + 2] = attr[3 * e + 2];
    }
}

// ======================= GELU ==============================================
__device__ __forceinline__ float gelu_f(float x) {
    float x3 = x * x * x;
    float u = 0.7978845608028654f * (x + 0.044715f * x3);
    return 0.5f * x * (1.0f + tanhf(u));
}

// ======================= HMMA GEMM common ===================================
#define SROW2 72

__device__ __forceinline__ void mma16816(float* c,
    uint32_t a0, uint32_t a1, uint32_t a2, uint32_t a3,
    uint32_t b0, uint32_t b1) {
    asm volatile(
        "mma.sync.aligned.m16n8k16.row.col.f32.bf16.bf16.f32 "
        "{%0,%1,%2,%3}, {%4,%5,%6,%7}, {%8,%9}, {%0,%1,%2,%3};"
        : "+f"(c[0]), "+f"(c[1]), "+f"(c[2]), "+f"(c[3])
        : "r"(a0), "r"(a1), "r"(a2), "r"(a3), "r"(b0), "r"(b1));
}

__device__ __forceinline__ void ldsm_x4(uint32_t& r0, uint32_t& r1,
                                        uint32_t& r2, uint32_t& r3, uint32_t addr) {
    asm volatile("ldmatrix.sync.aligned.m8n8.x4.shared.b16 {%0,%1,%2,%3}, [%4];"
                 : "=r"(r0), "=r"(r1), "=r"(r2), "=r"(r3) : "r"(addr));
}

__device__ __forceinline__ uint32_t smem_u32(const void* p) {
    return (uint32_t)__cvta_generic_to_shared(p);
}

__device__ __forceinline__ void stage_slab_A128(
    const __nv_bfloat16* Ahi, const __nv_bfloat16* Alo,
    __nv_bfloat16* sAh, __nv_bfloat16* sAl, int m0, int M, int slab, int tid)
{
    int row = tid >> 1;
    int u0  = (tid & 1) * 4;
    int gr  = m0 + row;
    bool ok = gr < M;
    const uint4* ah = (const uint4*)(Ahi + (size_t)gr * 128 + slab * 64);
    const uint4* al = (const uint4*)(Alo + (size_t)gr * 128 + slab * 64);
    uint4 z = make_uint4(0u, 0u, 0u, 0u);
    #pragma unroll
    for (int u = u0; u < u0 + 4; u++) {
        *(uint4*)(&sAh[row * SROW2 + u * 8]) = ok ? ah[u] : z;
        *(uint4*)(&sAl[row * SROW2 + u * 8]) = ok ? al[u] : z;
    }
}

__device__ __forceinline__ void stage_slab_A64(
    const __nv_bfloat16* Ahi, const __nv_bfloat16* Alo,
    __nv_bfloat16* sAh, __nv_bfloat16* sAl, int m0, int M, int slab, int tid)
{
    int row = tid >> 2;
    int u0  = (tid & 3) * 2;
    int gr  = m0 + row;
    bool ok = gr < M;
    const uint4* ah = (const uint4*)(Ahi + (size_t)gr * 128 + slab * 64);
    const uint4* al = (const uint4*)(Alo + (size_t)gr * 128 + slab * 64);
    uint4 z = make_uint4(0u, 0u, 0u, 0u);
    #pragma unroll
    for (int u = u0; u < u0 + 2; u++) {
        *(uint4*)(&sAh[row * SROW2 + u * 8]) = ok ? ah[u] : z;
        *(uint4*)(&sAl[row * SROW2 + u * 8]) = ok ? al[u] : z;
    }
}

__device__ __forceinline__ void stage_slab_B(
    const __nv_bfloat16* Bhi, const __nv_bfloat16* Blo,
    __nv_bfloat16* sBh, __nv_bfloat16* sBl, int Nout, int slab, int tid)
{
    int row = tid >> 1;
    if (row < Nout) {
        int u0 = (tid & 1) * 4;
        const uint4* bh = (const uint4*)(Bhi + (size_t)row * 128 + slab * 64);
        const uint4* bl = (const uint4*)(Blo + (size_t)row * 128 + slab * 64);
        #pragma unroll
        for (int u = u0; u < u0 + 4; u++) {
            *(uint4*)(&sBh[row * SROW2 + u * 8]) = bh[u];
            *(uint4*)(&sBl[row * SROW2 + u * 8]) = bl[u];
        }
    }
}

__device__ __forceinline__ void mainloop_slab(
    const __nv_bfloat16* sAh, const __nv_bfloat16* sAl,
    const __nv_bfloat16* sBh, const __nv_bfloat16* sBl,
    float acc[2][8][4], int mt, int lane, int ntBeg, int ntN)
{
    uint32_t aAh = smem_u32(sAh), aAl = smem_u32(sAl);
    uint32_t aBh = smem_u32(sBh), aBl = smem_u32(sBl);
    int arow = lane & 15, akh = 8 * (lane >> 4);
    int brow = lane & 7;
    int bsel = lane >> 4;
    int bk   = 8 * ((lane >> 3) & 1);

    for (int kt = 0; kt < 64; kt += 16) {
        uint32_t ah[2][4], al[2][4];
        #pragma unroll
        for (int mi = 0; mi < 2; mi++) {
            int aoff = (mt + mi * 16 + arow) * SROW2 + akh + kt;
            ldsm_x4(ah[mi][0], ah[mi][1], ah[mi][2], ah[mi][3], aAh + (uint32_t)aoff * 2);
            ldsm_x4(al[mi][0], al[mi][1], al[mi][2], al[mi][3], aAl + (uint32_t)aoff * 2);
        }
        #pragma unroll
        for (int p = 0; p < 4; p++) {
            if (2 * p >= ntN) break;
            int nt = ntBeg + 2 * p + bsel;
            int boff = (nt * 8 + brow) * SROW2 + bk + kt;
            uint32_t bh0, bh1, bh2, bh3, bl0, bl1, bl2, bl3;
            ldsm_x4(bh0, bh1, bh2, bh3, aBh + (uint32_t)boff * 2);
            ldsm_x4(bl0, bl1, bl2, bl3, aBl + (uint32_t)boff * 2);
            #pragma unroll
            for (int mi = 0; mi < 2; mi++) {
                mma16816(acc[mi][2 * p + 0], ah[mi][0], ah[mi][1], ah[mi][2], ah[mi][3], bh0, bh1);
                mma16816(acc[mi][2 * p + 0], ah[mi][0], ah[mi][1], ah[mi][2], ah[mi][3], bl0, bl1);
                mma16816(acc[mi][2 * p + 0], al[mi][0], al[mi][1], al[mi][2], al[mi][3], bh0, bh1);
                mma16816(acc[mi][2 * p + 1], ah[mi][0], ah[mi][1], ah[mi][2], ah[mi][3], bh2, bh3);
                mma16816(acc[mi][2 * p + 1], ah[mi][0], ah[mi][1], ah[mi][2], ah[mi][3], bl2, bl3);
                mma16816(acc[mi][2 * p + 1], al[mi][0], al[mi][1], al[mi][2], al[mi][3], bh2, bh3);
            }
        }
    }
}

// ======================= mma_gemm: 64-row CTAs ==============================
#define OFF3_AH 0
#define OFF3_AL 9216
#define OFF3_BH 18432
#define OFF3_BL 36864
#define MMA_SMEM3 55296

__global__ __launch_bounds__(256, 2) void mma_gemm(
    const __nv_bfloat16* __restrict__ Ahi, const __nv_bfloat16* __restrict__ Alo,
    const __nv_bfloat16* __restrict__ Bhi, const __nv_bfloat16* __restrict__ Blo,
    const float* __restrict__ bias, const float* __restrict__ res,
    float* __restrict__ C, __nv_bfloat16* __restrict__ Chi, __nv_bfloat16* __restrict__ Clo,
    int M, int Nout, int act)
{
    extern __shared__ char smem[];
    __nv_bfloat16* sAh = (__nv_bfloat16*)(smem + OFF3_AH);
    __nv_bfloat16* sAl = (__nv_bfloat16*)(smem + OFF3_AL);
    __nv_bfloat16* sBh = (__nv_bfloat16*)(smem + OFF3_BH);
    __nv_bfloat16* sBl = (__nv_bfloat16*)(smem + OFF3_BL);
    int tid = threadIdx.x;
    int m0 = blockIdx.x * 64;

    int lane = tid & 31, wid = tid >> 5;
    int grp = lane >> 2, qd = lane & 3;
    int mt = (wid >> 2) * 32;
    int NT = Nout >> 3;
    int ntBeg = (wid & 3) * (NT >> 2);
    int ntN   = NT >> 2;

    float acc[2][8][4];
    #pragma unroll
    for (int mi = 0; mi < 2; mi++)
        #pragma unroll
        for (int i = 0; i < 8; i++)
            #pragma unroll
            for (int j = 0; j < 4; j++) acc[mi][i][j] = 0.f;

    #pragma unroll
    for (int s = 0; s < 2; s++) {
        if (s) __syncthreads();
        stage_slab_A64(Ahi, Alo, sAh, sAl, m0, M, s, tid);
        stage_slab_B(Bhi, Blo, sBh, sBl, Nout, s, tid);
        __syncthreads();
        mainloop_slab(sAh, sAl, sBh, sBl, acc, mt, lane, ntBeg, ntN);
    }

    #pragma unroll
    for (int mi = 0; mi < 2; mi++) {
        #pragma unroll
        for (int t = 0; t < 8; t++) {
            if (t >= ntN) break;
            int col = (ntBeg + t) * 8 + 2 * qd;
            float bsum0 = bias ? bias[col]     : 0.f;
            float bsum1 = bias ? bias[col + 1] : 0.f;
            #pragma unroll
            for (int half = 0; half < 2; half++) {
                int row = m0 + mt + mi * 16 + grp + half * 8;
                if (row >= M) continue;
                float v0 = acc[mi][t][half * 2 + 0] + bsum0;
                float v1 = acc[mi][t][half * 2 + 1] + bsum1;
                if (act) { v0 = gelu_f(v0); v1 = gelu_f(v1); }
                size_t base = (size_t)row * Nout + col;
                if (res) { v0 += res[base]; v1 += res[base + 1]; }
                *(float2*)(C + base) = make_float2(v0, v1);
                if (Chi) {
                    __nv_bfloat16 h0 = __float2bfloat16(v0);
                    __nv_bfloat16 h1 = __float2bfloat16(v1);
                    __nv_bfloat162 hh; hh.x = h0; hh.y = h1;
                    __nv_bfloat162 ll;
                    ll.x = __float2bfloat16(v0 - __bfloat162float(h0));
                    ll.y = __float2bfloat16(v1 - __bfloat162float(h1));
                    *(__nv_bfloat162*)(Chi + base) = hh;
                    *(__nv_bfloat162*)(Clo + base) = ll;
                }
            }
        }
    }
}

// ======================= qkvs_gemm: 128-row CTAs, 2 CTAs/SM =================
#define OFF2_AH 0
#define OFF2_AL 18432
#define OFF2_BH 36864
#define OFF2_BL 55296
#define MMA_SMEM2 73728

struct QkvsPtrs {
    const __nv_bfloat16 *bh[4], *bl[4];
    float* c[4];
};

__global__ __launch_bounds__(256, 2) void qkvs_gemm(
    const __nv_bfloat16* __restrict__ Ahi, const __nv_bfloat16* __restrict__ Alo,
    QkvsPtrs pp, int M)
{
    extern __shared__ char smem[];
    __nv_bfloat16* sAh = (__nv_bfloat16*)(smem + OFF2_AH);
    __nv_bfloat16* sAl = (__nv_bfloat16*)(smem + OFF2_AL);
    __nv_bfloat16* sBh = (__nv_bfloat16*)(smem + OFF2_BH);
    __nv_bfloat16* sBl = (__nv_bfloat16*)(smem + OFF2_BL);
    int tid = threadIdx.x;
    int m0 = blockIdx.x * 128;
    int sel = blockIdx.y;

    int lane = tid & 31, wid = tid >> 5;
    int grp = lane >> 2, qd = lane & 3;
    int mt = (wid >> 1) * 32;
    int ntBeg = (wid & 1) * 8;

    float acc[2][8][4];
    #pragma unroll
    for (int mi = 0; mi < 2; mi++)
        #pragma unroll
        for (int i = 0; i < 8; i++)
            #pragma unroll
            for (int j = 0; j < 4; j++) acc[mi][i][j] = 0.f;

    #pragma unroll
    for (int s = 0; s < 2; s++) {
        if (s) __syncthreads();
        stage_slab_A128(Ahi, Alo, sAh, sAl, m0, M, s, tid);
        stage_slab_B(pp.bh[sel], pp.bl[sel], sBh, sBl, HID, s, tid);
        __syncthreads();
        mainloop_slab(sAh, sAl, sBh, sBl, acc, mt, lane, ntBeg, 8);
    }

    float* C = pp.c[sel];
    #pragma unroll
    for (int mi = 0; mi < 2; mi++) {
        #pragma unroll
        for (int t = 0; t < 8; t++) {
            int col = (ntBeg + t) * 8 + 2 * qd;
            #pragma unroll
            for (int half = 0; half < 2; half++) {
                int row = m0 + mt + mi * 16 + grp + half * 8;
                if (row >= M) continue;
                size_t base = (size_t)row * HID + col;
                *(float2*)(C + base) = make_float2(acc[mi][t][half * 2], acc[mi][t][half * 2 + 1]);
            }
        }
    }
}

// ===== edge attention: fixed-shift softmax (no online-max recurrence) =======
// softmax is shift-invariant: exp(a-C)/sum(exp(a-C)) exact for constant C.
#define ALPHA_SHIFT 30.0f

__global__ __launch_bounds__(128) void attn_kernel(
    const float* __restrict__ q, const float* __restrict__ k,
    const float* __restrict__ v, const float* __restrict__ skip,
    const float* __restrict__ We, float* __restrict__ out,
    __nv_bfloat16* __restrict__ outhi, __nv_bfloat16* __restrict__ outlo)
{
    __shared__ float we_s[HID * 3];
    int tid = threadIdx.x;
    for (int i = tid; i < HID * 3; i += blockDim.x) we_s[i] = We[i];
    __syncthreads();

    int warp = blockIdx.x * (blockDim.x >> 5) + (tid >> 5);
    if (warp >= N_NODES) return;
    int lane = tid & 31;
    int col  = (lane >> 3) * DH + (lane & 7) * 4;

    float wr[12];
    #pragma unroll
    for (int i = 0; i < 4; i++)
        #pragma unroll
        for (int c = 0; c < 3; c++)
            wr[i * 3 + c] = we_s[3 * (col + i) + c];

    float4 qv = *(const float4*)(q + (size_t)warp * HID + col);

    float ssum = 0.f, ox = 0.f, oy = 0.f, oz = 0.f, ow = 0.f;

    int e0 = g_off[warp], e1 = g_off[warp + 1];
    int e = e0;
    for (; e + 4 <= e1; e += 4) {
        int srcs[4];
        float at[4][3];
        float4 kvs[4], vvs[4];
        #pragma unroll
        for (int j = 0; j < 4; j++) srcs[j] = g_ssrc[e + j];
        #pragma unroll
        for (int j = 0; j < 4; j++) {
            at[j][0] = g_sattr[3 * (e + j) + 0];
            at[j][1] = g_sattr[3 * (e + j) + 1];
            at[j][2] = g_sattr[3 * (e + j) + 2];
        }
        #pragma unroll
        for (int j = 0; j < 4; j++) {
            kvs[j] = *(const float4*)(k + (size_t)srcs[j] * HID + col);
            vvs[j] = *(const float4*)(v + (size_t)srcs[j] * HID + col);
        }

        float ec[4][4], d[4];
        #pragma unroll
        for (int j = 0; j < 4; j++) {
            ec[j][0] = fmaf(at[j][0], wr[0], fmaf(at[j][1], wr[1],  at[j][2] * wr[2]));
            ec[j][1] = fmaf(at[j][0], wr[3], fmaf(at[j][1], wr[4],  at[j][2] * wr[5]));
            ec[j][2] = fmaf(at[j][0], wr[6], fmaf(at[j][1], wr[7],  at[j][2] * wr[8]));
            ec[j][3] = fmaf(at[j][0], wr[9], fmaf(at[j][1], wr[10], at[j][2] * wr[11]));
            d[j] = qv.x * (kvs[j].x + ec[j][0]) + qv.y * (kvs[j].y + ec[j][1])
                 + qv.z * (kvs[j].z + ec[j][2]) + qv.w * (kvs[j].w + ec[j][3]);
        }
        #pragma unroll
        for (int st = 1; st <= 4; st <<= 1) {
            #pragma unroll
            for (int j = 0; j < 4; j++)
                d[j] += __shfl_xor_sync(0xffffffffu, d[j], st);
        }
        #pragma unroll
        for (int j = 0; j < 4; j++) {
            float p = __expf(fmaf(d[j], 0.17677669529663687f, -ALPHA_SHIFT));
            ssum += p;
            ox = fmaf(p, vvs[j].x + ec[j][0], ox);
            oy = fmaf(p, vvs[j].y + ec[j][1], oy);
            oz = fmaf(p, vvs[j].z + ec[j][2], oz);
            ow = fmaf(p, vvs[j].w + ec[j][3], ow);
        }
    }
    for (; e < e1; e++) {
        int src = g_ssrc[e];
        float a0 = g_sattr[3 * e + 0];
        float a1 = g_sattr[3 * e + 1];
        float a2 = g_sattr[3 * e + 2];
        float4 kv = *(const float4*)(k + (size_t)src * HID + col);
        float4 vv = *(const float4*)(v + (size_t)src * HID + col);
        float ec0 = fmaf(a0, wr[0], fmaf(a1, wr[1],  a2 * wr[2]));
        float ec1 = fmaf(a0, wr[3], fmaf(a1, wr[4],  a2 * wr[5]));
        float ec2 = fmaf(a0, wr[6], fmaf(a1, wr[7],  a2 * wr[8]));
        float ec3 = fmaf(a0, wr[9], fmaf(a1, wr[10], a2 * wr[11]));
        float dot = qv.x * (kv.x + ec0) + qv.y * (kv.y + ec1)
                  + qv.z * (kv.z + ec2) + qv.w * (kv.w + ec3);
        dot += __shfl_xor_sync(0xffffffffu, dot, 1);
        dot += __shfl_xor_sync(0xffffffffu, dot, 2);
        dot += __shfl_xor_sync(0xffffffffu, dot, 4);
        float p = __expf(fmaf(dot, 0.17677669529663687f, -ALPHA_SHIFT));
        ssum += p;
        ox = fmaf(p, vv.x + ec0, ox);
        oy = fmaf(p, vv.y + ec1, oy);
        oz = fmaf(p, vv.z + ec2, oz);
        ow = fmaf(p, vv.w + ec3, ow);
    }

    float inv = 1.0f / fmaxf(ssum, 1e-36f);
    float4 sk = *(const float4*)(skip + (size_t)warp * HID + col);
    float o0 = ox * inv + sk.x, o1 = oy * inv + sk.y;
    float o2 = oz * inv + sk.z, o3 = ow * inv + sk.w;
    // zero-edge node: ssum==0 -> o* are 0, inv huge but 0*inv = 0. Guard NaN:
    if (ssum == 0.f) { o0 = sk.x; o1 = sk.y; o2 = sk.z; o3 = sk.w; }
    size_t base = (size_t)warp * HID + col;
    *(float4*)(out + base) = make_float4(o0, o1, o2, o3);

    float vs[4] = {o0, o1, o2, o3};
    #pragma unroll
    for (int pr = 0; pr < 2; pr++) {
        float v0 = vs[pr * 2], v1 = vs[pr * 2 + 1];
        __nv_bfloat16 h0 = __float2bfloat16(v0);
        __nv_bfloat16 h1 = __float2bfloat16(v1);
        __nv_bfloat162 hh; hh.x = h0; hh.y = h1;
        __nv_bfloat162 ll;
        ll.x = __float2bfloat16(v0 - __bfloat162float(h0));
        ll.y = __float2bfloat16(v1 - __bfloat162float(h1));
        *(__nv_bfloat162*)(outhi + base + pr * 2) = hh;
        *(__nv_bfloat162*)(outlo + base + pr * 2) = ll;
    }
}

// ======================= launch =============================================
static inline void run_mm(cudaStream_t s,
                          const __nv_bfloat16* Ahi, const __nv_bfloat16* Alo,
                          const __nv_bfloat16* Bhi, const __nv_bfloat16* Blo,
                          const float* bias, const float* res,
                          float* C, __nv_bfloat16* Chi, __nv_bfloat16* Clo,
                          int M, int Nout, int act) {
    int grid = (M + 63) / 64;
    mma_gemm<<<grid, 256, MMA_SMEM3, s>>>(Ahi, Alo, Bhi, Blo, bias, res, C, Chi, Clo, M, Nout, act);
}

extern "C" void kernel_launch(void* const* d_in, const int* in_sizes, int n_in,
                              void* d_out, int out_size) {
    const float* x    = (const float*)d_in[0];
    const int*   ei   = (const int*)  d_in[1];
    const float* attr = (const float*)d_in[2];
    const float* Wq1 = (const float*)d_in[3],  *Wk1 = (const float*)d_in[4];
    const float* Wv1 = (const float*)d_in[5],  *We1 = (const float*)d_in[6];
    const float* Ws1 = (const float*)d_in[7];
    const float* M1a = (const float*)d_in[8],  *b1a = (const float*)d_in[9];
    const float* M1b = (const float*)d_in[10], *b1b = (const float*)d_in[11];
    const float* Wq2 = (const float*)d_in[12], *Wk2 = (const float*)d_in[13];
    const float* Wv2 = (const float*)d_in[14], *We2 = (const float*)d_in[15];
    const float* Ws2 = (const float*)d_in[16];
    const float* M2a = (const float*)d_in[17], *b2a = (const float*)d_in[18];
    const float* M2b = (const float*)d_in[19], *b2b = (const float*)d_in[20];
    const float* Wf1 = (const float*)d_in[21], *bf1 = (const float*)d_in[22];
    const float* Wf2 = (const float*)d_in[23], *bf2 = (const float*)d_in[24];
    float* out = (float*)d_out;

    float *q, *k, *v, *sk, *h, *t1, *t2;
    cudaGetSymbolAddress((void**)&q,  g_q);
    cudaGetSymbolAddress((void**)&k,  g_k);
    cudaGetSymbolAddress((void**)&v,  g_v);
    cudaGetSymbolAddress((void**)&sk, g_sk);
    cudaGetSymbolAddress((void**)&h,  g_h);
    cudaGetSymbolAddress((void**)&t1, g_t1);
    cudaGetSymbolAddress((void**)&t2, g_t2);

    __nv_bfloat16 *xhi, *xlo, *hhi, *hlo, *t1hi, *t1lo, *t2hi, *t2lo, *whi, *wlo;
    cudaGetSymbolAddress((void**)&xhi,  g_xhi);
    cudaGetSymbolAddress((void**)&xlo,  g_xlo);
    cudaGetSymbolAddress((void**)&hhi,  g_hhi);
    cudaGetSymbolAddress((void**)&hlo,  g_hlo);
    cudaGetSymbolAddress((void**)&t1hi, g_t1hi);
    cudaGetSymbolAddress((void**)&t1lo, g_t1lo);
    cudaGetSymbolAddress((void**)&t2hi, g_t2hi);
    cudaGetSymbolAddress((void**)&t2lo, g_t2lo);
    cudaGetSymbolAddress((void**)&whi,  g_whi);
    cudaGetSymbolAddress((void**)&wlo,  g_wlo);

    cudaFuncSetAttribute(mma_gemm,  cudaFuncAttributeMaxDynamicSharedMemorySize, MMA_SMEM3);
    cudaFuncSetAttribute(qkvs_gemm, cudaFuncAttributeMaxDynamicSharedMemorySize, MMA_SMEM2);

    static cudaStream_t s_side = nullptr;
    static cudaEvent_t ev_fork = nullptr, ev_join = nullptr;
    if (!s_side) {
        cudaStreamCreateWithFlags(&s_side, cudaStreamNonBlocking);
        cudaEventCreateWithFlags(&ev_fork, cudaEventDisableTiming);
        cudaEventCreateWithFlags(&ev_join, cudaEventDisableTiming);
    }

    cudaStream_t s = 0;
    #define WHI(i) (whi + (i) * 16384)
    #define WLO(i) (wlo + (i) * 16384)

    int gblocks = (N_NODES + 127) / 128;
    int ablocks = (N_NODES * 32 + 127) / 128;

    // ---- fork: side stream runs the edge-sort chain concurrently ----
    cudaEventRecord(ev_fork, s);
    cudaStreamWaitEvent(s_side, ev_fork, 0);

    zero_deg_kernel<<<(N_NODES + 255) / 256, 256, 0, s_side>>>();
    hist_kernel<<<(N_EDGES + 255) / 256, 256, 0, s_side>>>(ei);

    WPtrs wp;
    const float* wsrc[14] = {Wq1, Wk1, Wv1, Ws1, M1a, M1b, Wq2, Wk2, Wv2, Ws2, M2a, M2b, Wf1, Wf2};
    for (int i = 0; i < 14; i++) wp.p[i] = wsrc[i];
    bigsplit_kernel<<<WSPLIT_BLOCKS + XSPLIT_BLOCKS, 256, 0, s>>>(wp, x);

    QkvsPtrs p1;
    for (int i = 0; i < 4; i++) { p1.bh[i] = WHI(i); p1.bl[i] = WLO(i); }
    p1.c[0] = q; p1.c[1] = k; p1.c[2] = v; p1.c[3] = sk;
    qkvs_gemm<<<dim3(gblocks, 4), 256, MMA_SMEM2, s>>>(xhi, xlo, p1, N_NODES);

    scan_s1<<<SCAN_NBLK, 1024, 0, s_side>>>();
    scan_s2<<<1, 64, 0, s_side>>>();
    scan_s3<<<(N_NODES + 255) / 256, 256, 0, s_side>>>();
    scatter_kernel<<<(N_EDGES + 255) / 256, 256, 0, s_side>>>(ei, attr);

    cudaEventRecord(ev_join, s_side);
    cudaStreamWaitEvent(s, ev_join, 0);

    // layer 1
    attn_kernel<<<ablocks, 128, 0, s>>>(q, k, v, sk, We1, h, hhi, hlo);
    run_mm(s, hhi,  hlo,  WHI(4), WLO(4), b1a, nullptr, t1, t1hi, t1lo, N_NODES, HID, 1);
    run_mm(s, t1hi, t1lo, WHI(5), WLO(5), b1b, h,       t2, t2hi, t2lo, N_NODES, HID, 1);

    // layer 2
    QkvsPtrs p2;
    for (int i = 0; i < 4; i++) { p2.bh[i] = WHI(6 + i); p2.bl[i] = WLO(6 + i); }
    p2.c[0] = q; p2.c[1] = k; p2.c[2] = v; p2.c[3] = sk;
    qkvs_gemm<<<dim3(gblocks, 4), 256, MMA_SMEM2, s>>>(t2hi, t2lo, p2, N_NODES);
    attn_kernel<<<ablocks, 128, 0, s>>>(q, k, v, sk, We2, h, hhi, hlo);
    run_mm(s, hhi,  hlo,  WHI(10), WLO(10), b2a, nullptr, t1, t1hi, t1lo, N_NODES, HID, 1);
    run_mm(s, t1hi, t1lo, WHI(11), WLO(11), b2b, h,       t2, t2hi, t2lo, N_NODES, HID, 1);

    // final MLP
    run_mm(s, t2hi, t2lo, WHI(12), WLO(12), bf1, nullptr, t1, t1hi, t1lo, N_NODES, HID, 1);
    run_mm(s, t1hi, t1lo, WHI(13), WLO(13), bf2, nullptr, out, nullptr, nullptr, N_NODES, OUTD, 1);
}

// round 15
// speedup vs baseline: 1.0686x; 1.0422x over previous
#include <cuda_runtime.h>
#include <cuda_bf16.h>
#include <math.h>
#include <stdint.h>

#define N_NODES 50000
#define N_EDGES 800000
#define HID     128
#define NHEAD   4
#define DH      32
#define OUTD    64
#define HALFN   25088   // half split, divisible by 128 and 64

// ======================= scratch (device globals) ===========================
__device__ float g_q [N_NODES * HID];
__device__ float g_k [N_NODES * HID];
__device__ float g_v [N_NODES * HID];
__device__ float g_sk[N_NODES * HID];
__device__ float g_q2 [N_NODES * HID];
__device__ float g_k2 [N_NODES * HID];
__device__ float g_v2 [N_NODES * HID];
__device__ float g_sk2[N_NODES * HID];
__device__ float g_h [N_NODES * HID];
__device__ float g_t1[N_NODES * HID];
__device__ float g_t2[N_NODES * HID];
__device__ int   g_deg [N_NODES];
__device__ int   g_off [N_NODES + 1];
__device__ int   g_cur [N_NODES];
__device__ int   g_ssrc[N_EDGES];
__device__ float g_sattr[N_EDGES * 3];

#define SCAN_NBLK 49
__device__ int g_bsum[SCAN_NBLK];
__device__ int g_bpre[SCAN_NBLK];

__device__ __nv_bfloat16 g_xhi [N_NODES * HID];
__device__ __nv_bfloat16 g_xlo [N_NODES * HID];
__device__ __nv_bfloat16 g_hhi [N_NODES * HID];
__device__ __nv_bfloat16 g_hlo [N_NODES * HID];
__device__ __nv_bfloat16 g_t1hi[N_NODES * HID];
__device__ __nv_bfloat16 g_t1lo[N_NODES * HID];
__device__ __nv_bfloat16 g_t2hi[N_NODES * HID];
__device__ __nv_bfloat16 g_t2lo[N_NODES * HID];
__device__ __nv_bfloat16 g_whi[14 * 16384];
__device__ __nv_bfloat16 g_wlo[14 * 16384];

// ============ fused: weight split + x split (one launch) ====================
struct WPtrs { const float* p[14]; };

#define WSPLIT_BLOCKS 864
#define XSPLIT_BLOCKS 25000

__global__ void bigsplit_kernel(WPtrs wp, const float* __restrict__ x) {
    int b = blockIdx.x;
    if (b < WSPLIT_BLOCKS) {
        int mi, cb;
        if (b < 832) { mi = b >> 6; cb = b & 63; }
        else         { mi = 13;     cb = b - 832; }
        int i = cb * 256 + threadIdx.x;
        int n = (mi == 13) ? 8192 : 16384;
        if (i < n) {
            float v = wp.p[mi][i];
            __nv_bfloat16 h = __float2bfloat16(v);
            g_whi[mi * 16384 + i] = h;
            g_wlo[mi * 16384 + i] = __float2bfloat16(v - __bfloat162float(h));
        }
    } else {
        int i = (b - WSPLIT_BLOCKS) * 256 + threadIdx.x;
        float v = x[i];
        __nv_bfloat16 h = __float2bfloat16(v);
        g_xhi[i] = h;
        g_xlo[i] = __float2bfloat16(v - __bfloat162float(h));
    }
}

// ======================= edge sorting =======================================
__global__ void zero_deg_kernel() {
    int i = blockIdx.x * blockDim.x + threadIdx.x;
    if (i < N_NODES) g_deg[i] = 0;
}

__global__ void hist_kernel(const int* __restrict__ ei) {
    int e = blockIdx.x * blockDim.x + threadIdx.x;
    if (e < N_EDGES) atomicAdd(&g_deg[ei[N_EDGES + e]], 1);
}

__global__ __launch_bounds__(1024) void scan_s1() {
    __shared__ int wsum[32];
    int tid = threadIdx.x, lane = tid & 31, wid = tid >> 5;
    int i = blockIdx.x * 1024 + tid;
    int v = (i < N_NODES) ? g_deg[i] : 0;
    int x = v;
    #pragma unroll
    for (int d = 1; d < 32; d <<= 1) {
        int y = __shfl_up_sync(0xffffffffu, x, d);
        if (lane >= d) x += y;
    }
    if (lane == 31) wsum[wid] = x;
    __syncthreads();
    if (wid == 0) {
        int s = wsum[lane];
        #pragma unroll
        for (int d = 1; d < 32; d <<= 1) {
            int y = __shfl_up_sync(0xffffffffu, s, d);
            if (lane >= d) s += y;
        }
        wsum[lane] = s;
    }
    __syncthreads();
    int incl = x + (wid > 0 ? wsum[wid - 1] : 0);
    if (i < N_NODES) g_off[i] = incl - v;
    if (tid == 1023) g_bsum[blockIdx.x] = incl;
}

__global__ void scan_s2() {
    __shared__ int w0sum;
    int tid = threadIdx.x;
    int lane = tid & 31, wid = tid >> 5;
    int v = (tid < SCAN_NBLK) ? g_bsum[tid] : 0;
    int x = v;
    #pragma unroll
    for (int d = 1; d < 32; d <<= 1) {
        int y = __shfl_up_sync(0xffffffffu, x, d);
        if (lane >= d) x += y;
    }
    if (wid == 0 && lane == 31) w0sum = x;
    __syncthreads();
    int incl = x + (wid ? w0sum : 0);
    if (tid < SCAN_NBLK) g_bpre[tid] = incl - v;
    if (tid == SCAN_NBLK - 1) g_off[N_NODES] = incl;
}

__global__ void scan_s3() {
    int i = blockIdx.x * blockDim.x + threadIdx.x;
    if (i < N_NODES) {
        int o = g_off[i] + g_bpre[i >> 10];
        g_off[i] = o;
        g_cur[i] = o;
    }
}

__global__ void scatter_kernel(const int* __restrict__ ei, const float* __restrict__ attr) {
    int e = blockIdx.x * blockDim.x + threadIdx.x;
    if (e < N_EDGES) {
        int dst = ei[N_EDGES + e];
        int pos = atomicAdd(&g_cur[dst], 1);
        g_ssrc[pos] = ei[e];
        g_sattr[3 * pos + 0] = attr[3 * e + 0];
        g_sattr[3 * pos + 1] = attr[3 * e + 1];
        g_sattr[3 * pos + 2] = attr[3 * e + 2];
    }
}

// ======================= GELU ==============================================
__device__ __forceinline__ float gelu_f(float x) {
    float x3 = x * x * x;
    float u = 0.7978845608028654f * (x + 0.044715f * x3);
    return 0.5f * x * (1.0f + tanhf(u));
}

// ======================= HMMA GEMM common ===================================
#define SROW2 72

__device__ __forceinline__ void mma16816(float* c,
    uint32_t a0, uint32_t a1, uint32_t a2, uint32_t a3,
    uint32_t b0, uint32_t b1) {
    asm volatile(
        "mma.sync.aligned.m16n8k16.row.col.f32.bf16.bf16.f32 "
        "{%0,%1,%2,%3}, {%4,%5,%6,%7}, {%8,%9}, {%0,%1,%2,%3};"
        : "+f"(c[0]), "+f"(c[1]), "+f"(c[2]), "+f"(c[3])
        : "r"(a0), "r"(a1), "r"(a2), "r"(a3), "r"(b0), "r"(b1));
}

__device__ __forceinline__ void ldsm_x4(uint32_t& r0, uint32_t& r1,
                                        uint32_t& r2, uint32_t& r3, uint32_t addr) {
    asm volatile("ldmatrix.sync.aligned.m8n8.x4.shared.b16 {%0,%1,%2,%3}, [%4];"
                 : "=r"(r0), "=r"(r1), "=r"(r2), "=r"(r3) : "r"(addr));
}

__device__ __forceinline__ uint32_t smem_u32(const void* p) {
    return (uint32_t)__cvta_generic_to_shared(p);
}

__device__ __forceinline__ void stage_slab_A128(
    const __nv_bfloat16* Ahi, const __nv_bfloat16* Alo,
    __nv_bfloat16* sAh, __nv_bfloat16* sAl, int m0, int M, int slab, int tid)
{
    int row = tid >> 1;
    int u0  = (tid & 1) * 4;
    int gr  = m0 + row;
    bool ok = gr < M;
    const uint4* ah = (const uint4*)(Ahi + (size_t)gr * 128 + slab * 64);
    const uint4* al = (const uint4*)(Alo + (size_t)gr * 128 + slab * 64);
    uint4 z = make_uint4(0u, 0u, 0u, 0u);
    #pragma unroll
    for (int u = u0; u < u0 + 4; u++) {
        *(uint4*)(&sAh[row * SROW2 + u * 8]) = ok ? ah[u] : z;
        *(uint4*)(&sAl[row * SROW2 + u * 8]) = ok ? al[u] : z;
    }
}

__device__ __forceinline__ void stage_slab_A64(
    const __nv_bfloat16* Ahi, const __nv_bfloat16* Alo,
    __nv_bfloat16* sAh, __nv_bfloat16* sAl, int m0, int M, int slab, int tid)
{
    int row = tid >> 2;
    int u0  = (tid & 3) * 2;
    int gr  = m0 + row;
    bool ok = gr < M;
    const uint4* ah = (const uint4*)(Ahi + (size_t)gr * 128 + slab * 64);
    const uint4* al = (const uint4*)(Alo + (size_t)gr * 128 + slab * 64);
    uint4 z = make_uint4(0u, 0u, 0u, 0u);
    #pragma unroll
    for (int u = u0; u < u0 + 2; u++) {
        *(uint4*)(&sAh[row * SROW2 + u * 8]) = ok ? ah[u] : z;
        *(uint4*)(&sAl[row * SROW2 + u * 8]) = ok ? al[u] : z;
    }
}

__device__ __forceinline__ void stage_slab_B(
    const __nv_bfloat16* Bhi, const __nv_bfloat16* Blo,
    __nv_bfloat16* sBh, __nv_bfloat16* sBl, int Nout, int slab, int tid)
{
    int row = tid >> 1;
    if (row < Nout) {
        int u0 = (tid & 1) * 4;
        const uint4* bh = (const uint4*)(Bhi + (size_t)row * 128 + slab * 64);
        const uint4* bl = (const uint4*)(Blo + (size_t)row * 128 + slab * 64);
        #pragma unroll
        for (int u = u0; u < u0 + 4; u++) {
            *(uint4*)(&sBh[row * SROW2 + u * 8]) = bh[u];
            *(uint4*)(&sBl[row * SROW2 + u * 8]) = bl[u];
        }
    }
}

__device__ __forceinline__ void mainloop_slab(
    const __nv_bfloat16* sAh, const __nv_bfloat16* sAl,
    const __nv_bfloat16* sBh, const __nv_bfloat16* sBl,
    float acc[2][8][4], int mt, int lane, int ntBeg, int ntN)
{
    uint32_t aAh = smem_u32(sAh), aAl = smem_u32(sAl);
    uint32_t aBh = smem_u32(sBh), aBl = smem_u32(sBl);
    int arow = lane & 15, akh = 8 * (lane >> 4);
    int brow = lane & 7;
    int bsel = lane >> 4;
    int bk   = 8 * ((lane >> 3) & 1);

    for (int kt = 0; kt < 64; kt += 16) {
        uint32_t ah[2][4], al[2][4];
        #pragma unroll
        for (int mi = 0; mi < 2; mi++) {
            int aoff = (mt + mi * 16 + arow) * SROW2 + akh + kt;
            ldsm_x4(ah[mi][0], ah[mi][1], ah[mi][2], ah[mi][3], aAh + (uint32_t)aoff * 2);
            ldsm_x4(al[mi][0], al[mi][1], al[mi][2], al[mi][3], aAl + (uint32_t)aoff * 2);
        }
        #pragma unroll
        for (int p = 0; p < 4; p++) {
            if (2 * p >= ntN) break;
            int nt = ntBeg + 2 * p + bsel;
            int boff = (nt * 8 + brow) * SROW2 + bk + kt;
            uint32_t bh0, bh1, bh2, bh3, bl0, bl1, bl2, bl3;
            ldsm_x4(bh0, bh1, bh2, bh3, aBh + (uint32_t)boff * 2);
            ldsm_x4(bl0, bl1, bl2, bl3, aBl + (uint32_t)boff * 2);
            #pragma unroll
            for (int mi = 0; mi < 2; mi++) {
                mma16816(acc[mi][2 * p + 0], ah[mi][0], ah[mi][1], ah[mi][2], ah[mi][3], bh0, bh1);
                mma16816(acc[mi][2 * p + 0], ah[mi][0], ah[mi][1], ah[mi][2], ah[mi][3], bl0, bl1);
                mma16816(acc[mi][2 * p + 0], al[mi][0], al[mi][1], al[mi][2], al[mi][3], bh0, bh1);
                mma16816(acc[mi][2 * p + 1], ah[mi][0], ah[mi][1], ah[mi][2], ah[mi][3], bh2, bh3);
                mma16816(acc[mi][2 * p + 1], ah[mi][0], ah[mi][1], ah[mi][2], ah[mi][3], bl2, bl3);
                mma16816(acc[mi][2 * p + 1], al[mi][0], al[mi][1], al[mi][2], al[mi][3], bh2, bh3);
            }
        }
    }
}

// ======================= mma_gemm: 64-row CTAs, row-range ====================
#define OFF3_AH 0
#define OFF3_AL 9216
#define OFF3_BH 18432
#define OFF3_BL 36864
#define MMA_SMEM3 55296

__global__ __launch_bounds__(256, 2) void mma_gemm(
    const __nv_bfloat16* __restrict__ Ahi, const __nv_bfloat16* __restrict__ Alo,
    const __nv_bfloat16* __restrict__ Bhi, const __nv_bfloat16* __restrict__ Blo,
    const float* __restrict__ bias, const float* __restrict__ res,
    float* __restrict__ C, __nv_bfloat16* __restrict__ Chi, __nv_bfloat16* __restrict__ Clo,
    int mStart, int M, int Nout, int act)
{
    extern __shared__ char smem[];
    __nv_bfloat16* sAh = (__nv_bfloat16*)(smem + OFF3_AH);
    __nv_bfloat16* sAl = (__nv_bfloat16*)(smem + OFF3_AL);
    __nv_bfloat16* sBh = (__nv_bfloat16*)(smem + OFF3_BH);
    __nv_bfloat16* sBl = (__nv_bfloat16*)(smem + OFF3_BL);
    int tid = threadIdx.x;
    int m0 = mStart + blockIdx.x * 64;

    int lane = tid & 31, wid = tid >> 5;
    int grp = lane >> 2, qd = lane & 3;
    int mt = (wid >> 2) * 32;
    int NT = Nout >> 3;
    int ntBeg = (wid & 3) * (NT >> 2);
    int ntN   = NT >> 2;

    float acc[2][8][4];
    #pragma unroll
    for (int mi = 0; mi < 2; mi++)
        #pragma unroll
        for (int i = 0; i < 8; i++)
            #pragma unroll
            for (int j = 0; j < 4; j++) acc[mi][i][j] = 0.f;

    #pragma unroll
    for (int s = 0; s < 2; s++) {
        if (s) __syncthreads();
        stage_slab_A64(Ahi, Alo, sAh, sAl, m0, M, s, tid);
        stage_slab_B(Bhi, Blo, sBh, sBl, Nout, s, tid);
        __syncthreads();
        mainloop_slab(sAh, sAl, sBh, sBl, acc, mt, lane, ntBeg, ntN);
    }

    #pragma unroll
    for (int mi = 0; mi < 2; mi++) {
        #pragma unroll
        for (int t = 0; t < 8; t++) {
            if (t >= ntN) break;
            int col = (ntBeg + t) * 8 + 2 * qd;
            float bsum0 = bias ? bias[col]     : 0.f;
            float bsum1 = bias ? bias[col + 1] : 0.f;
            #pragma unroll
            for (int half = 0; half < 2; half++) {
                int row = m0 + mt + mi * 16 + grp + half * 8;
                if (row >= M) continue;
                float v0 = acc[mi][t][half * 2 + 0] + bsum0;
                float v1 = acc[mi][t][half * 2 + 1] + bsum1;
                if (act) { v0 = gelu_f(v0); v1 = gelu_f(v1); }
                size_t base = (size_t)row * Nout + col;
                if (res) { v0 += res[base]; v1 += res[base + 1]; }
                *(float2*)(C + base) = make_float2(v0, v1);
                if (Chi) {
                    __nv_bfloat16 h0 = __float2bfloat16(v0);
                    __nv_bfloat16 h1 = __float2bfloat16(v1);
                    __nv_bfloat162 hh; hh.x = h0; hh.y = h1;
                    __nv_bfloat162 ll;
                    ll.x = __float2bfloat16(v0 - __bfloat162float(h0));
                    ll.y = __float2bfloat16(v1 - __bfloat162float(h1));
                    *(__nv_bfloat162*)(Chi + base) = hh;
                    *(__nv_bfloat162*)(Clo + base) = ll;
                }
            }
        }
    }
}

// ======================= qkvs_gemm: 128-row CTAs, row-range ==================
#define OFF2_AH 0
#define OFF2_AL 18432
#define OFF2_BH 36864
#define OFF2_BL 55296
#define MMA_SMEM2 73728

struct QkvsPtrs {
    const __nv_bfloat16 *bh[4], *bl[4];
    float* c[4];
};

__global__ __launch_bounds__(256, 2) void qkvs_gemm(
    const __nv_bfloat16* __restrict__ Ahi, const __nv_bfloat16* __restrict__ Alo,
    QkvsPtrs pp, int mStart, int M)
{
    extern __shared__ char smem[];
    __nv_bfloat16* sAh = (__nv_bfloat16*)(smem + OFF2_AH);
    __nv_bfloat16* sAl = (__nv_bfloat16*)(smem + OFF2_AL);
    __nv_bfloat16* sBh = (__nv_bfloat16*)(smem + OFF2_BH);
    __nv_bfloat16* sBl = (__nv_bfloat16*)(smem + OFF2_BL);
    int tid = threadIdx.x;
    int m0 = mStart + blockIdx.x * 128;
    int sel = blockIdx.y;

    int lane = tid & 31, wid = tid >> 5;
    int grp = lane >> 2, qd = lane & 3;
    int mt = (wid >> 1) * 32;
    int ntBeg = (wid & 1) * 8;

    float acc[2][8][4];
    #pragma unroll
    for (int mi = 0; mi < 2; mi++)
        #pragma unroll
        for (int i = 0; i < 8; i++)
            #pragma unroll
            for (int j = 0; j < 4; j++) acc[mi][i][j] = 0.f;

    #pragma unroll
    for (int s = 0; s < 2; s++) {
        if (s) __syncthreads();
        stage_slab_A128(Ahi, Alo, sAh, sAl, m0, M, s, tid);
        stage_slab_B(pp.bh[sel], pp.bl[sel], sBh, sBl, HID, s, tid);
        __syncthreads();
        mainloop_slab(sAh, sAl, sBh, sBl, acc, mt, lane, ntBeg, 8);
    }

    float* C = pp.c[sel];
    #pragma unroll
    for (int mi = 0; mi < 2; mi++) {
        #pragma unroll
        for (int t = 0; t < 8; t++) {
            int col = (ntBeg + t) * 8 + 2 * qd;
            #pragma unroll
            for (int half = 0; half < 2; half++) {
                int row = m0 + mt + mi * 16 + grp + half * 8;
                if (row >= M) continue;
                size_t base = (size_t)row * HID + col;
                *(float2*)(C + base) = make_float2(acc[mi][t][half * 2], acc[mi][t][half * 2 + 1]);
            }
        }
    }
}

// ======= edge attention: dual accumulators (R12 best), node-range ===========
__global__ __launch_bounds__(128) void attn_kernel(
    const float* __restrict__ q, const float* __restrict__ k,
    const float* __restrict__ v, const float* __restrict__ skip,
    const float* __restrict__ We, float* __restrict__ out,
    __nv_bfloat16* __restrict__ outhi, __nv_bfloat16* __restrict__ outlo,
    int nodeStart, int nodeEnd)
{
    __shared__ float we_s[HID * 3];
    int tid = threadIdx.x;
    for (int i = tid; i < HID * 3; i += blockDim.x) we_s[i] = We[i];
    __syncthreads();

    int warp = nodeStart + blockIdx.x * (blockDim.x >> 5) + (tid >> 5);
    if (warp >= nodeEnd) return;
    int lane = tid & 31;
    int col  = (lane >> 3) * DH + (lane & 7) * 4;

    float wr[12];
    #pragma unroll
    for (int i = 0; i < 4; i++)
        #pragma unroll
        for (int c = 0; c < 3; c++)
            wr[i * 3 + c] = we_s[3 * (col + i) + c];

    float4 qv = *(const float4*)(q + (size_t)warp * HID + col);

    float mA = -INFINITY, sA = 0.f, oAx = 0.f, oAy = 0.f, oAz = 0.f, oAw = 0.f;
    float mB = -INFINITY, sB = 0.f, oBx = 0.f, oBy = 0.f, oBz = 0.f, oBw = 0.f;

    int e0 = g_off[warp], e1 = g_off[warp + 1];
    int e = e0;
    for (; e + 2 <= e1; e += 2) {
        int s0 = g_ssrc[e], s1 = g_ssrc[e + 1];
        float a00 = g_sattr[3 * e + 0], a01 = g_sattr[3 * e + 1], a02 = g_sattr[3 * e + 2];
        float a10 = g_sattr[3 * e + 3], a11 = g_sattr[3 * e + 4], a12 = g_sattr[3 * e + 5];
        float4 kv0 = *(const float4*)(k + (size_t)s0 * HID + col);
        float4 vv0 = *(const float4*)(v + (size_t)s0 * HID + col);
        float4 kv1 = *(const float4*)(k + (size_t)s1 * HID + col);
        float4 vv1 = *(const float4*)(v + (size_t)s1 * HID + col);

        float e00 = fmaf(a00, wr[0], fmaf(a01, wr[1],  a02 * wr[2]));
        float e01 = fmaf(a00, wr[3], fmaf(a01, wr[4],  a02 * wr[5]));
        float e02 = fmaf(a00, wr[6], fmaf(a01, wr[7],  a02 * wr[8]));
        float e03 = fmaf(a00, wr[9], fmaf(a01, wr[10], a02 * wr[11]));
        float e10 = fmaf(a10, wr[0], fmaf(a11, wr[1],  a12 * wr[2]));
        float e11 = fmaf(a10, wr[3], fmaf(a11, wr[4],  a12 * wr[5]));
        float e12 = fmaf(a10, wr[6], fmaf(a11, wr[7],  a12 * wr[8]));
        float e13 = fmaf(a10, wr[9], fmaf(a11, wr[10], a12 * wr[11]));

        float d0 = qv.x * (kv0.x + e00) + qv.y * (kv0.y + e01)
                 + qv.z * (kv0.z + e02) + qv.w * (kv0.w + e03);
        float d1 = qv.x * (kv1.x + e10) + qv.y * (kv1.y + e11)
                 + qv.z * (kv1.z + e12) + qv.w * (kv1.w + e13);
        d0 += __shfl_xor_sync(0xffffffffu, d0, 1);
        d1 += __shfl_xor_sync(0xffffffffu, d1, 1);
        d0 += __shfl_xor_sync(0xffffffffu, d0, 2);
        d1 += __shfl_xor_sync(0xffffffffu, d1, 2);
        d0 += __shfl_xor_sync(0xffffffffu, d0, 4);
        d1 += __shfl_xor_sync(0xffffffffu, d1, 4);
        float al0 = d0 * 0.17677669529663687f;
        float al1 = d1 * 0.17677669529663687f;

        {
            float nm = fmaxf(mA, al0);
            float sc = __expf(mA - nm);
            float p  = __expf(al0 - nm);
            sA = sA * sc + p;
            oAx = oAx * sc + p * (vv0.x + e00);
            oAy = oAy * sc + p * (vv0.y + e01);
            oAz = oAz * sc + p * (vv0.z + e02);
            oAw = oAw * sc + p * (vv0.w + e03);
            mA = nm;
        }
        {
            float nm = fmaxf(mB, al1);
            float sc = __expf(mB - nm);
            float p  = __expf(al1 - nm);
            sB = sB * sc + p;
            oBx = oBx * sc + p * (vv1.x + e10);
            oBy = oBy * sc + p * (vv1.y + e11);
            oBz = oBz * sc + p * (vv1.z + e12);
            oBw = oBw * sc + p * (vv1.w + e13);
            mB = nm;
        }
    }
    if (e < e1) {
        int src = g_ssrc[e];
        float a0 = g_sattr[3 * e + 0];
        float a1 = g_sattr[3 * e + 1];
        float a2 = g_sattr[3 * e + 2];
        float4 kv = *(const float4*)(k + (size_t)src * HID + col);
        float4 vv = *(const float4*)(v + (size_t)src * HID + col);
        float ec0 = fmaf(a0, wr[0], fmaf(a1, wr[1],  a2 * wr[2]));
        float ec1 = fmaf(a0, wr[3], fmaf(a1, wr[4],  a2 * wr[5]));
        float ec2 = fmaf(a0, wr[6], fmaf(a1, wr[7],  a2 * wr[8]));
        float ec3 = fmaf(a0, wr[9], fmaf(a1, wr[10], a2 * wr[11]));
        float dot = qv.x * (kv.x + ec0) + qv.y * (kv.y + ec1)
                  + qv.z * (kv.z + ec2) + qv.w * (kv.w + ec3);
        dot += __shfl_xor_sync(0xffffffffu, dot, 1);
        dot += __shfl_xor_sync(0xffffffffu, dot, 2);
        dot += __shfl_xor_sync(0xffffffffu, dot, 4);
        float alpha = dot * 0.17677669529663687f;
        float nm = fmaxf(mA, alpha);
        float sc = __expf(mA - nm);
        float p  = __expf(alpha - nm);
        sA = sA * sc + p;
        oAx = oAx * sc + p * (vv.x + ec0);
        oAy = oAy * sc + p * (vv.y + ec1);
        oAz = oAz * sc + p * (vv.z + ec2);
        oAw = oAw * sc + p * (vv.w + ec3);
        mA = nm;
    }

    {
        float nm = fmaxf(mA, mB);
        float wa = (mA == -INFINITY) ? 0.f : __expf(mA - nm);
        float wb = (mB == -INFINITY) ? 0.f : __expf(mB - nm);
        sA = sA * wa + sB * wb;
        oAx = oAx * wa + oBx * wb;
        oAy = oAy * wa + oBy * wb;
        oAz = oAz * wa + oBz * wb;
        oAw = oAw * wa + oBw * wb;
    }

    float inv = 1.0f / fmaxf(sA, 1e-16f);
    float4 sk = *(const float4*)(skip + (size_t)warp * HID + col);
    float o0 = oAx * inv + sk.x, o1 = oAy * inv + sk.y;
    float o2 = oAz * inv + sk.z, o3 = oAw * inv + sk.w;
    size_t base = (size_t)warp * HID + col;
    *(float4*)(out + base) = make_float4(o0, o1, o2, o3);

    float vs[4] = {o0, o1, o2, o3};
    #pragma unroll
    for (int pr = 0; pr < 2; pr++) {
        float v0 = vs[pr * 2], v1 = vs[pr * 2 + 1];
        __nv_bfloat16 h0 = __float2bfloat16(v0);
        __nv_bfloat16 h1 = __float2bfloat16(v1);
        __nv_bfloat162 hh; hh.x = h0; hh.y = h1;
        __nv_bfloat162 ll;
        ll.x = __float2bfloat16(v0 - __bfloat162float(h0));
        ll.y = __float2bfloat16(v1 - __bfloat162float(h1));
        *(__nv_bfloat162*)(outhi + base + pr * 2) = hh;
        *(__nv_bfloat162*)(outlo + base + pr * 2) = ll;
    }
}

// ======================= launch =============================================
static inline void run_mm_r(cudaStream_t s,
                            const __nv_bfloat16* Ahi, const __nv_bfloat16* Alo,
                            const __nv_bfloat16* Bhi, const __nv_bfloat16* Blo,
                            const float* bias, const float* res,
                            float* C, __nv_bfloat16* Chi, __nv_bfloat16* Clo,
                            int mStart, int mEnd, int Nout, int act) {
    int grid = (mEnd - mStart + 63) / 64;
    mma_gemm<<<grid, 256, MMA_SMEM3, s>>>(Ahi, Alo, Bhi, Blo, bias, res, C, Chi, Clo,
                                          mStart, mEnd, Nout, act);
}

extern "C" void kernel_launch(void* const* d_in, const int* in_sizes, int n_in,
                              void* d_out, int out_size) {
    const float* x    = (const float*)d_in[0];
    const int*   ei   = (const int*)  d_in[1];
    const float* attr = (const float*)d_in[2];
    const float* Wq1 = (const float*)d_in[3],  *Wk1 = (const float*)d_in[4];
    const float* Wv1 = (const float*)d_in[5],  *We1 = (const float*)d_in[6];
    const float* Ws1 = (const float*)d_in[7];
    const float* M1a = (const float*)d_in[8],  *b1a = (const float*)d_in[9];
    const float* M1b = (const float*)d_in[10], *b1b = (const float*)d_in[11];
    const float* Wq2 = (const float*)d_in[12], *Wk2 = (const float*)d_in[13];
    const float* Wv2 = (const float*)d_in[14], *We2 = (const float*)d_in[15];
    const float* Ws2 = (const float*)d_in[16];
    const float* M2a = (const float*)d_in[17], *b2a = (const float*)d_in[18];
    const float* M2b = (const float*)d_in[19], *b2b = (const float*)d_in[20];
    const float* Wf1 = (const float*)d_in[21], *bf1 = (const float*)d_in[22];
    const float* Wf2 = (const float*)d_in[23], *bf2 = (const float*)d_in[24];
    float* out = (float*)d_out;

    float *q, *k, *v, *sk, *q2, *k2, *v2, *sk2, *h, *t1, *t2;
    cudaGetSymbolAddress((void**)&q,   g_q);
    cudaGetSymbolAddress((void**)&k,   g_k);
    cudaGetSymbolAddress((void**)&v,   g_v);
    cudaGetSymbolAddress((void**)&sk,  g_sk);
    cudaGetSymbolAddress((void**)&q2,  g_q2);
    cudaGetSymbolAddress((void**)&k2,  g_k2);
    cudaGetSymbolAddress((void**)&v2,  g_v2);
    cudaGetSymbolAddress((void**)&sk2, g_sk2);
    cudaGetSymbolAddress((void**)&h,   g_h);
    cudaGetSymbolAddress((void**)&t1,  g_t1);
    cudaGetSymbolAddress((void**)&t2,  g_t2);

    __nv_bfloat16 *xhi, *xlo, *hhi, *hlo, *t1hi, *t1lo, *t2hi, *t2lo, *whi, *wlo;
    cudaGetSymbolAddress((void**)&xhi,  g_xhi);
    cudaGetSymbolAddress((void**)&xlo,  g_xlo);
    cudaGetSymbolAddress((void**)&hhi,  g_hhi);
    cudaGetSymbolAddress((void**)&hlo,  g_hlo);
    cudaGetSymbolAddress((void**)&t1hi, g_t1hi);
    cudaGetSymbolAddress((void**)&t1lo, g_t1lo);
    cudaGetSymbolAddress((void**)&t2hi, g_t2hi);
    cudaGetSymbolAddress((void**)&t2lo, g_t2lo);
    cudaGetSymbolAddress((void**)&whi,  g_whi);
    cudaGetSymbolAddress((void**)&wlo,  g_wlo);

    cudaFuncSetAttribute(mma_gemm,  cudaFuncAttributeMaxDynamicSharedMemorySize, MMA_SMEM3);
    cudaFuncSetAttribute(qkvs_gemm, cudaFuncAttributeMaxDynamicSharedMemorySize, MMA_SMEM2);

    static cudaStream_t s_side = nullptr;
    static cudaEvent_t ev_fork = nullptr, ev_join = nullptr;
    static cudaEvent_t e1 = nullptr, e2 = nullptr, e3 = nullptr, e4 = nullptr;
    if (!s_side) {
        cudaStreamCreateWithFlags(&s_side, cudaStreamNonBlocking);
        cudaEventCreateWithFlags(&ev_fork, cudaEventDisableTiming);
        cudaEventCreateWithFlags(&ev_join, cudaEventDisableTiming);
        cudaEventCreateWithFlags(&e1, cudaEventDisableTiming);
        cudaEventCreateWithFlags(&e2, cudaEventDisableTiming);
        cudaEventCreateWithFlags(&e3, cudaEventDisableTiming);
        cudaEventCreateWithFlags(&e4, cudaEventDisableTiming);
    }

    cudaStream_t s = 0;
    #define WHI(i) (whi + (i) * 16384)
    #define WLO(i) (wlo + (i) * 16384)

    int abA = HALFN / 4;                       // 6272 blocks, nodes [0, HALFN)
    int abB = (N_NODES - HALFN + 3) / 4;       // 6228 blocks, nodes [HALFN, N)

    // ---- fork: side runs the edge-sort chain concurrently ----
    cudaEventRecord(ev_fork, s);
    cudaStreamWaitEvent(s_side, ev_fork, 0);

    zero_deg_kernel<<<(N_NODES + 255) / 256, 256, 0, s_side>>>();
    hist_kernel<<<(N_EDGES + 255) / 256, 256, 0, s_side>>>(ei);

    WPtrs wp;
    const float* wsrc[14] = {Wq1, Wk1, Wv1, Ws1, M1a, M1b, Wq2, Wk2, Wv2, Ws2, M2a, M2b, Wf1, Wf2};
    for (int i = 0; i < 14; i++) wp.p[i] = wsrc[i];
    bigsplit_kernel<<<WSPLIT_BLOCKS + XSPLIT_BLOCKS, 256, 0, s>>>(wp, x);

    // launch #4: layer-1 fused QKVS GEMM (full grid; ncu sentinel)
    QkvsPtrs p1;
    for (int i = 0; i < 4; i++) { p1.bh[i] = WHI(i); p1.bl[i] = WLO(i); }
    p1.c[0] = q; p1.c[1] = k; p1.c[2] = v; p1.c[3] = sk;
    qkvs_gemm<<<dim3((N_NODES + 127) / 128, 4), 256, MMA_SMEM2, s>>>(xhi, xlo, p1, 0, N_NODES);

    scan_s1<<<SCAN_NBLK, 1024, 0, s_side>>>();
    scan_s2<<<1, 64, 0, s_side>>>();
    scan_s3<<<(N_NODES + 255) / 256, 256, 0, s_side>>>();
    scatter_kernel<<<(N_EDGES + 255) / 256, 256, 0, s_side>>>(ei, attr);
    cudaEventRecord(ev_join, s_side);
    cudaStreamWaitEvent(s, ev_join, 0);

    QkvsPtrs p2;
    for (int i = 0; i < 4; i++) { p2.bh[i] = WHI(6 + i); p2.bl[i] = WLO(6 + i); }
    p2.c[0] = q2; p2.c[1] = k2; p2.c[2] = v2; p2.c[3] = sk2;

    // ===== layer 1 =====
    attn_kernel<<<abA, 128, 0, s>>>(q, k, v, sk, We1, h, hhi, hlo, 0, HALFN);
    cudaEventRecord(e1, s);
    // side: half-A MLP + qkvs2 while main runs attn1B
    cudaStreamWaitEvent(s_side, e1, 0);
    run_mm_r(s_side, hhi,  hlo,  WHI(4), WLO(4), b1a, nullptr, t1, t1hi, t1lo, 0, HALFN, HID, 1);
    run_mm_r(s_side, t1hi, t1lo, WHI(5), WLO(5), b1b, h,       t2, t2hi, t2lo, 0, HALFN, HID, 1);
    qkvs_gemm<<<dim3(HALFN / 128, 4), 256, MMA_SMEM2, s_side>>>(t2hi, t2lo, p2, 0, HALFN);
    cudaEventRecord(e2, s_side);
    // main: attn1B + half-B MLP + qkvs2B
    attn_kernel<<<abB, 128, 0, s>>>(q, k, v, sk, We1, h, hhi, hlo, HALFN, N_NODES);
    run_mm_r(s, hhi,  hlo,  WHI(4), WLO(4), b1a, nullptr, t1, t1hi, t1lo, HALFN, N_NODES, HID, 1);
    run_mm_r(s, t1hi, t1lo, WHI(5), WLO(5), b1b, h,       t2, t2hi, t2lo, HALFN, N_NODES, HID, 1);
    qkvs_gemm<<<dim3((N_NODES - HALFN + 127) / 128, 4), 256, MMA_SMEM2, s>>>(t2hi, t2lo, p2, HALFN, N_NODES);
    cudaStreamWaitEvent(s, e2, 0);

    // ===== layer 2 =====
    attn_kernel<<<abA, 128, 0, s>>>(q2, k2, v2, sk2, We2, h, hhi, hlo, 0, HALFN);
    cudaEventRecord(e3, s);
    // side: half-A tail (MLP2 + final MLP) while main runs attn2B
    cudaStreamWaitEvent(s_side, e3, 0);
    run_mm_r(s_side, hhi,  hlo,  WHI(10), WLO(10), b2a, nullptr, t1, t1hi, t1lo, 0, HALFN, HID, 1);
    run_mm_r(s_side, t1hi, t1lo, WHI(11), WLO(11), b2b, h,       t2, t2hi, t2lo, 0, HALFN, HID, 1);
    run_mm_r(s_side, t2hi, t2lo, WHI(12), WLO(12), bf1, nullptr, t1, t1hi, t1lo, 0, HALFN, HID, 1);
    run_mm_r(s_side, t1hi, t1lo, WHI(13), WLO(13), bf2, nullptr, out, nullptr, nullptr, 0, HALFN, OUTD, 1);
    cudaEventRecord(e4, s_side);
    // main: attn2B + half-B tail
    attn_kernel<<<abB, 128, 0, s>>>(q2, k2, v2, sk2, We2, h, hhi, hlo, HALFN, N_NODES);
    run_mm_r(s, hhi,  hlo,  WHI(10), WLO(10), b2a, nullptr, t1, t1hi, t1lo, HALFN, N_NODES, HID, 1);
    run_mm_r(s, t1hi, t1lo, WHI(11), WLO(11), b2b, h,       t2, t2hi, t2lo, HALFN, N_NODES, HID, 1);
    run_mm_r(s, t2hi, t2lo, WHI(12), WLO(12), bf1, nullptr, t1, t1hi, t1lo, HALFN, N_NODES, HID, 1);
    run_mm_r(s, t1hi, t1lo, WHI(13), WLO(13), bf2, nullptr, out, nullptr, nullptr, HALFN, N_NODES, OUTD, 1);
    cudaStreamWaitEvent(s, e4, 0);
}